// round 8
// baseline (speedup 1.0000x reference)
#include <cuda_runtime.h>
#include <cstdint>

// Problem constants (fixed by reference)
#define BATCH   4
#define NTOK    8192
#define DIM     768
#define SEGW    512
#define NSEG    16
#define MG      256       // gathered (even) rows per segment
#define TM      128       // Q rows per CTA tile
#define KC      32        // phase-1 k-chunk width
#define NCHUNK  (DIM/KC)  // 24
#define THREADS 512

#define DCH     192       // phase-3 d chunk width
#define KSLAB   32        // phase-3 V slab rows
#define NSLAB   (MG/KSLAB)// 8

// Pair layout: values (k, k+4) stored adjacent as float2.
// float2 strides chosen ≡ 4 (mod 16) for conflict-free 64-bit fragment loads.
#define KS2 20            // K tile row stride (f2): 16 data + 4 pad
#define PS2 132           // P row stride (f2): 128 data + 4 pad
#define VS2 196           // V pair-row stride (f2): 192 data + 4 pad
#define VG2 (4*VS2)       // V 8-row-group stride (f2)

#define KCHF2   (MG*KS2)          // 5120 f2 per K buffer (x2 buffers alias P)
#define P_FLOATS (TM*PS2*2)       // 33792 floats
#define V_OFF2  (P_FLOATS/2)      // f2 offset of V area
#define VSLAB2  (16*VS2)          // 3136 f2 per V slab buffer
#define SMEM_FLOATS (P_FLOATS + 2*VSLAB2*2)   // 46336
#define SMEM_BYTES  (SMEM_FLOATS*4)           // 185344

__device__ __forceinline__ uint32_t f2tf32(float f) {
    uint32_t u;
    asm("cvt.rna.tf32.f32 %0, %1;" : "=r"(u) : "f"(f));
    return u;
}

__device__ __forceinline__ void mma8(float c[4], const uint32_t a[4], const uint32_t b[2]) {
    asm volatile(
        "mma.sync.aligned.m16n8k8.row.col.f32.tf32.tf32.f32 "
        "{%0,%1,%2,%3}, {%4,%5,%6,%7}, {%8,%9}, {%0,%1,%2,%3};\n"
        : "+f"(c[0]), "+f"(c[1]), "+f"(c[2]), "+f"(c[3])
        : "r"(a[0]), "r"(a[1]), "r"(a[2]), "r"(a[3]), "r"(b[0]), "r"(b[1]));
}

__global__ __launch_bounds__(THREADS, 1)
void dilated_attn_kernel(const float* __restrict__ x, float* __restrict__ y)
{
    extern __shared__ float smf[];
    uint2* sm2 = (uint2*)smf;
    const int tid  = threadIdx.x;
    const int lane = tid & 31;
    const int wid  = tid >> 5;     // 0..15

    const int mtile = blockIdx.x & 1;       // 2 x 128-row tiles per problem
    const int pid   = blockIdx.x >> 1;      // 64 problems
    const long segbase = (long)(pid >> 4) * NTOK + (long)(pid & 15) * SEGW;
    const int  m0 = mtile * TM;

    // Warp layout (both GEMMs): 4 m-warps x 4 n-warps
    const int wm  = wid & 3;
    const int wn  = wid >> 2;
    const int ln4 = lane >> 2;   // fragment group 0..7
    const int lc4 = lane & 3;    // thread-in-group 0..3
    const int sx  = lc4 ^ (ln4 & 3);   // swizzled pair-slot for fragment reads

    // ============ Phase 1: S = Q K^T (128 x 256), double-buffered K chunks ============
    float acc[2][8][4];
    #pragma unroll
    for (int mt = 0; mt < 2; mt++)
        #pragma unroll
        for (int nt = 0; nt < 8; nt++)
            #pragma unroll
            for (int i = 0; i < 4; i++)
                acc[mt][nt][i] = 0.f;

    // K-fill: item = (row r, k-group g of 8). Pairs (k,k+4) -> slots (p ^ (r&3)).
    // Prologue: chunk 0 -> buf0
    #pragma unroll
    for (int j = 0; j < 2; j++) {
        int i = j * THREADS + tid;      // 0..1023
        int r = i >> 2, g = i & 3;
        const float* src = x + (size_t)(segbase + 2 * r) * DIM + g * 8;
        float4 lo = *(const float4*)src;
        float4 hi = *(const float4*)(src + 4);
        uint32_t ul[4] = { f2tf32(lo.x), f2tf32(lo.y), f2tf32(lo.z), f2tf32(lo.w) };
        uint32_t uh[4] = { f2tf32(hi.x), f2tf32(hi.y), f2tf32(hi.z), f2tf32(hi.w) };
        int xw = r & 3;
        uint2* base = sm2 + r * KS2 + g * 4;
        *(uint4*)(base)     = make_uint4(ul[xw],   uh[xw],   ul[1^xw], uh[1^xw]);
        *(uint4*)(base + 2) = make_uint4(ul[2^xw], uh[2^xw], ul[3^xw], uh[3^xw]);
    }
    __syncthreads();

    float4 stg[4];
    for (int kc = 0; kc < NCHUNK; kc++) {
        const uint2* cur = sm2 + (kc & 1 ? KCHF2 : 0);
        const bool pf = (kc + 1 < NCHUNK);
        if (pf) {
            const int kd = (kc + 1) * KC;
            #pragma unroll
            for (int j = 0; j < 2; j++) {
                int i = j * THREADS + tid;
                int r = i >> 2, g = i & 3;
                const float* src = x + (size_t)(segbase + 2 * r) * DIM + kd + g * 8;
                stg[2*j]   = *(const float4*)src;
                stg[2*j+1] = *(const float4*)(src + 4);
            }
        }
        const uint2* abase = cur + (m0 + wm * 32 + ln4) * KS2 + sx;
        const uint2* bbase = cur + (wn * 64 + ln4) * KS2 + sx;
        #pragma unroll
        for (int ks = 0; ks < 4; ks++) {
            const int off = ks * 4;
            uint32_t a[2][4];
            #pragma unroll
            for (int mt = 0; mt < 2; mt++) {
                uint2 pa  = abase[(mt * 16)     * KS2 + off];
                uint2 pa8 = abase[(mt * 16 + 8) * KS2 + off];
                a[mt][0] = pa.x;  a[mt][1] = pa8.x;
                a[mt][2] = pa.y;  a[mt][3] = pa8.y;
            }
            #pragma unroll
            for (int nt = 0; nt < 8; nt++) {
                uint2 pb = bbase[nt * 8 * KS2 + off];
                uint32_t bf[2] = { pb.x, pb.y };
                mma8(acc[0][nt], a[0], bf);
                mma8(acc[1][nt], a[1], bf);
            }
        }
        if (pf) {
            uint2* dst = sm2 + (kc & 1 ? 0 : KCHF2);
            #pragma unroll
            for (int j = 0; j < 2; j++) {
                int i = j * THREADS + tid;
                int r = i >> 2, g = i & 3;
                float4 lo = stg[2*j], hi = stg[2*j+1];
                uint32_t ul[4] = { f2tf32(lo.x), f2tf32(lo.y), f2tf32(lo.z), f2tf32(lo.w) };
                uint32_t uh[4] = { f2tf32(hi.x), f2tf32(hi.y), f2tf32(hi.z), f2tf32(hi.w) };
                int xw = r & 3;
                uint2* base = dst + r * KS2 + g * 4;
                *(uint4*)(base)     = make_uint4(ul[xw],   uh[xw],   ul[1^xw], uh[1^xw]);
                *(uint4*)(base + 2) = make_uint4(ul[2^xw], uh[2^xw], ul[3^xw], uh[3^xw]);
            }
        }
        __syncthreads();
    }

    // ============ Phase 2: scale + softmax into P (pair layout, tf32 on final write) ============
    const float scale = 0.03608439182435161f;  // 768^-0.5
    {
        const int xr = ln4 & 3;
        const int p  = (2 * lc4) & 3;          // even
        const int comp = lc4 >> 1;
        #pragma unroll
        for (int mt = 0; mt < 2; mt++) {
            int r = wm * 32 + mt * 16 + ln4;
            float* row0 = smf + r * (PS2 * 2);
            float* row8 = row0 + 8 * (PS2 * 2);
            #pragma unroll
            for (int nt = 0; nt < 8; nt++) {
                int gg = wn * 8 + nt;
                int iA = (gg * 4 + (p ^ xr)) * 2 + comp;
                int iB = (gg * 4 + ((p + 1) ^ xr)) * 2 + comp;
                row0[iA] = acc[mt][nt][0] * scale;
                row0[iB] = acc[mt][nt][1] * scale;
                row8[iA] = acc[mt][nt][2] * scale;
                row8[iB] = acc[mt][nt][3] * scale;
            }
        }
    }
    __syncthreads();

    // Row softmax (column-permutation invariant): warp w -> rows w*8..w*8+7
    #pragma unroll
    for (int rr = 0; rr < 8; rr++) {
        int row = wid * 8 + rr;
        float* pr = smf + row * (PS2 * 2);     // first 256 floats are the data
        float v[8];
        float mx = -1e30f;
        #pragma unroll
        for (int i = 0; i < 8; i++) { v[i] = pr[lane + 32 * i]; mx = fmaxf(mx, v[i]); }
        #pragma unroll
        for (int o = 16; o > 0; o >>= 1) mx = fmaxf(mx, __shfl_xor_sync(~0u, mx, o));
        float s = 0.f;
        #pragma unroll
        for (int i = 0; i < 8; i++) { v[i] = __expf(v[i] - mx); s += v[i]; }
        #pragma unroll
        for (int o = 16; o > 0; o >>= 1) s += __shfl_xor_sync(~0u, s, o);
        float inv = 1.f / s;
        #pragma unroll
        for (int i = 0; i < 8; i++)
            pr[lane + 32 * i] = __uint_as_float(f2tf32(v[i] * inv));
    }
    __syncthreads();

    // ============ Phase 3: out = P V (128 x 768), 4 d-chunks of 192, V in 32-row slabs ============
    // V pair layout: pairs across rows (k, k+4): [group g][pr][n] f2, no swizzle.
    for (int ch = 0; ch < 4; ch++) {
        const int d0 = ch * DCH;

        float o[2][6][4];
        #pragma unroll
        for (int mt = 0; mt < 2; mt++)
            #pragma unroll
            for (int nt = 0; nt < 6; nt++)
                #pragma unroll
                for (int i = 0; i < 4; i++)
                    o[mt][nt][i] = 0.f;

        // Prologue: slab 0 -> V buf0. Items: 16 pair-rows x 48 n-quads = 768.
        for (int i = tid; i < 768; i += THREADS) {
            int prall = i / 48, nc = i % 48;
            int g = prall >> 2, pr = prall & 3;
            int klo = g * 8 + pr;
            const float* s0 = x + (size_t)(segbase + 2 * klo) * DIM + d0 + nc * 4;
            float4 lo = *(const float4*)s0;
            float4 hi = *(const float4*)(s0 + 8 * DIM);   // row klo+4 = token +8
            uint2* base = sm2 + V_OFF2 + g * VG2 + pr * VS2 + nc * 4;
            *(uint4*)(base)     = make_uint4(f2tf32(lo.x), f2tf32(hi.x), f2tf32(lo.y), f2tf32(hi.y));
            *(uint4*)(base + 2) = make_uint4(f2tf32(lo.z), f2tf32(hi.z), f2tf32(lo.w), f2tf32(hi.w));
        }
        __syncthreads();

        float4 vst[4];
        for (int sl = 0; sl < NSLAB; sl++) {
            const uint2* vcur = sm2 + V_OFF2 + (sl & 1) * VSLAB2;
            const bool pf = (sl + 1 < NSLAB);
            if (pf) {
                const int rbase = (sl + 1) * KSLAB;
                #pragma unroll
                for (int j = 0; j < 2; j++) {
                    int i = j * THREADS + tid;
                    if (i < 768) {
                        int prall = i / 48, nc = i % 48;
                        int g = prall >> 2, pr = prall & 3;
                        int klo = rbase + g * 8 + pr;
                        const float* s0 = x + (size_t)(segbase + 2 * klo) * DIM + d0 + nc * 4;
                        vst[2*j]   = *(const float4*)s0;
                        vst[2*j+1] = *(const float4*)(s0 + 8 * DIM);
                    }
                }
            }
            const uint2* abase = sm2 + (wm * 32 + ln4) * PS2 + sl * 16 + sx;
            const uint2* bbase = vcur + lc4 * VS2 + wn * 48 + ln4;
            #pragma unroll
            for (int ks = 0; ks < 4; ks++) {
                uint32_t a[2][4];
                #pragma unroll
                for (int mt = 0; mt < 2; mt++) {
                    uint2 pa  = abase[(mt * 16)     * PS2 + ks * 4];
                    uint2 pa8 = abase[(mt * 16 + 8) * PS2 + ks * 4];
                    a[mt][0] = pa.x;  a[mt][1] = pa8.x;
                    a[mt][2] = pa.y;  a[mt][3] = pa8.y;
                }
                const uint2* bb0 = bbase + ks * VG2;
                #pragma unroll
                for (int nt = 0; nt < 6; nt++) {
                    uint2 pb = bb0[nt * 8];
                    uint32_t bf[2] = { pb.x, pb.y };
                    mma8(o[0][nt], a[0], bf);
                    mma8(o[1][nt], a[1], bf);
                }
            }
            if (pf) {
                uint2* dst = sm2 + V_OFF2 + ((sl + 1) & 1) * VSLAB2;
                #pragma unroll
                for (int j = 0; j < 2; j++) {
                    int i = j * THREADS + tid;
                    if (i < 768) {
                        int prall = i / 48, nc = i % 48;
                        int g = prall >> 2, pr = prall & 3;
                        float4 lo = vst[2*j], hi = vst[2*j+1];
                        uint2* base = dst + g * VG2 + pr * VS2 + nc * 4;
                        *(uint4*)(base)     = make_uint4(f2tf32(lo.x), f2tf32(hi.x), f2tf32(lo.y), f2tf32(hi.y));
                        *(uint4*)(base + 2) = make_uint4(f2tf32(lo.z), f2tf32(hi.z), f2tf32(lo.w), f2tf32(hi.w));
                    }
                }
            }
            __syncthreads();
        }

        // Epilogue: even (gathered) rows get results
        #pragma unroll
        for (int mt = 0; mt < 2; mt++)
            #pragma unroll
            for (int nt = 0; nt < 6; nt++) {
                int gr = m0 + wm * 32 + mt * 16 + ln4;
                int c  = d0 + wn * 48 + nt * 8 + 2 * lc4;
                long tok0 = segbase + 2 * (long)gr;
                long tok1 = segbase + 2 * (long)(gr + 8);
                *(float2*)(y + (size_t)tok0 * DIM + c) = make_float2(o[mt][nt][0], o[mt][nt][1]);
                *(float2*)(y + (size_t)tok1 * DIM + c) = make_float2(o[mt][nt][2], o[mt][nt][3]);
            }

        // Odd partner rows are exactly zero (this d-chunk)
        #pragma unroll
        for (int j = 0; j < 12; j++) {
            int i = j * THREADS + tid;
            int r = i / 48, c4 = i % 48;
            long tok = segbase + 2 * (long)(m0 + r) + 1;
            *(float4*)(y + (size_t)tok * DIM + d0 + c4 * 4) = make_float4(0.f, 0.f, 0.f, 0.f);
        }
        __syncthreads();
    }
}

extern "C" void kernel_launch(void* const* d_in, const int* in_sizes, int n_in,
                              void* d_out, int out_size)
{
    const float* x = (const float*)d_in[0];
    float* y = (float*)d_out;
    cudaFuncSetAttribute(dilated_attn_kernel,
                         cudaFuncAttributeMaxDynamicSharedMemorySize, SMEM_BYTES);
    dilated_attn_kernel<<<BATCH * NSEG * 2, THREADS, SMEM_BYTES>>>(x, y);
}

// round 9
// speedup vs baseline: 1.1850x; 1.1850x over previous
#include <cuda_runtime.h>
#include <cstdint>

// Problem constants (fixed by reference)
#define BATCH   4
#define NTOK    8192
#define DIM     768
#define SEGW    512
#define NSEG    16
#define MG      256       // gathered (even) rows per segment
#define TM      128       // Q rows per CTA tile
#define KC      32        // phase-1 k-chunk width
#define NCHUNK  (DIM/KC)  // 24
#define THREADS 256

#define DCH     192       // phase-3 d chunk width
#define KSLAB   32        // phase-3 V slab rows
#define NSLAB   (MG/KSLAB)// 8

// Padded smem strides (floats). k-major: stride%8==4; V n-major: stride%32==8.
#define K_STRIDE 36
#define P_STRIDE 260
#define V_STRIDE 200      // 192 + 8

#define KCHF    (MG*K_STRIDE)     // 9216 floats per K buffer (2 buffers alias P)
#define P_OFF   0
#define P_FLOATS (TM*P_STRIDE)    // 33280
#define V_OFF   P_FLOATS
#define VSLABF  (KSLAB*V_STRIDE)  // 6400
#define SMEM_FLOATS (V_OFF + 2*VSLABF)   // 46080
#define SMEM_BYTES  (SMEM_FLOATS * 4)    // 184320  (1 CTA/SM)

__device__ __forceinline__ uint32_t f2tf32(float f) {
    uint32_t u;
    asm("cvt.rna.tf32.f32 %0, %1;" : "=r"(u) : "f"(f));
    return u;
}

__device__ __forceinline__ void sts_tf32x4(float* dst, float4 v) {
    float4 w;
    w.x = __uint_as_float(f2tf32(v.x));
    w.y = __uint_as_float(f2tf32(v.y));
    w.z = __uint_as_float(f2tf32(v.z));
    w.w = __uint_as_float(f2tf32(v.w));
    *(float4*)dst = w;
}

__device__ __forceinline__ void mma8(float c[4], const uint32_t a[4], const uint32_t b[2]) {
    asm volatile(
        "mma.sync.aligned.m16n8k8.row.col.f32.tf32.tf32.f32 "
        "{%0,%1,%2,%3}, {%4,%5,%6,%7}, {%8,%9}, {%0,%1,%2,%3};\n"
        : "+f"(c[0]), "+f"(c[1]), "+f"(c[2]), "+f"(c[3])
        : "r"(a[0]), "r"(a[1]), "r"(a[2]), "r"(a[3]), "r"(b[0]), "r"(b[1]));
}

__global__ __launch_bounds__(THREADS, 1)
void dilated_attn_kernel(const float* __restrict__ x, float* __restrict__ y)
{
    extern __shared__ float sm[];
    uint32_t* smu = (uint32_t*)sm;
    const int tid  = threadIdx.x;
    const int lane = tid & 31;
    const int wid  = tid >> 5;     // 0..7

    const int mtile = blockIdx.x & 1;       // 2 x 128-row tiles per problem
    const int pid   = blockIdx.x >> 1;      // 64 problems
    const long segbase = (long)(pid >> 4) * NTOK + (long)(pid & 15) * SEGW;
    const int  m0 = mtile * TM;

    // Warp layout (both GEMMs): 2 m-warps x 4 n-warps, 64-row warp tiles
    const int wm  = wid & 1;
    const int wn  = wid >> 1;
    const int ln4 = lane >> 2;   // fragment group 0..7
    const int lc4 = lane & 3;    // thread-in-group 0..3

    // ============ Phase 1: S = Q K^T (128 x 256), double-buffered K chunks ============
    // Warp tile: 64 rows x 64 cols -> mt 0..3, nt 0..7
    float acc[4][8][4];
    #pragma unroll
    for (int mt = 0; mt < 4; mt++)
        #pragma unroll
        for (int nt = 0; nt < 8; nt++)
            #pragma unroll
            for (int i = 0; i < 4; i++)
                acc[mt][nt][i] = 0.f;

    // Prologue: chunk 0 -> buf0 (tf32-rounded at store)
    #pragma unroll
    for (int j = 0; j < 8; j++) {
        int idx = j * THREADS + tid;
        int r = idx >> 3, c4 = idx & 7;
        float4 v = *(const float4*)(x + (size_t)(segbase + 2 * r) * DIM + c4 * 4);
        sts_tf32x4(sm + r * K_STRIDE + c4 * 4, v);
    }
    __syncthreads();

    float4 stg[8];
    for (int kc = 0; kc < NCHUNK; kc++) {
        const uint32_t* cur = smu + (kc & 1 ? KCHF : 0);
        const bool pf = (kc + 1 < NCHUNK);
        if (pf) {
            const int kd = (kc + 1) * KC;
            #pragma unroll
            for (int j = 0; j < 8; j++) {
                int idx = j * THREADS + tid;
                int r = idx >> 3, c4 = idx & 7;
                stg[j] = *(const float4*)(x + (size_t)(segbase + 2 * r) * DIM + kd + c4 * 4);
            }
        }
        const uint32_t* abase = cur + (m0 + wm * 64 + ln4) * K_STRIDE + lc4;
        const uint32_t* bbase = cur + (wn * 64 + ln4) * K_STRIDE + lc4;
        #pragma unroll
        for (int ks = 0; ks < KC / 8; ks++) {
            const int kk = ks * 8;
            uint32_t a[4][4];
            #pragma unroll
            for (int mt = 0; mt < 4; mt++) {
                const uint32_t* ba = abase + mt * 16 * K_STRIDE + kk;
                a[mt][0] = ba[0];
                a[mt][1] = ba[8 * K_STRIDE];
                a[mt][2] = ba[4];
                a[mt][3] = ba[8 * K_STRIDE + 4];
            }
            #pragma unroll
            for (int nt = 0; nt < 8; nt++) {
                const uint32_t* bb = bbase + nt * 8 * K_STRIDE + kk;
                uint32_t bf[2] = { bb[0], bb[4] };
                #pragma unroll
                for (int mt = 0; mt < 4; mt++)
                    mma8(acc[mt][nt], a[mt], bf);
            }
        }
        if (pf) {
            float* dst = sm + (kc & 1 ? 0 : KCHF);
            #pragma unroll
            for (int j = 0; j < 8; j++) {
                int idx = j * THREADS + tid;
                int r = idx >> 3, c4 = idx & 7;
                sts_tf32x4(dst + r * K_STRIDE + c4 * 4, stg[j]);
            }
        }
        __syncthreads();
    }

    // ============ Phase 2: scale + softmax into P (tf32-rounded on final write) ============
    const float scale = 0.03608439182435161f;  // 768^-0.5
    #pragma unroll
    for (int mt = 0; mt < 4; mt++)
        #pragma unroll
        for (int nt = 0; nt < 8; nt++) {
            int r = wm * 64 + mt * 16 + ln4;
            int c = wn * 64 + nt * 8 + 2 * lc4;
            sm[P_OFF + r * P_STRIDE + c]           = acc[mt][nt][0] * scale;
            sm[P_OFF + r * P_STRIDE + c + 1]       = acc[mt][nt][1] * scale;
            sm[P_OFF + (r + 8) * P_STRIDE + c]     = acc[mt][nt][2] * scale;
            sm[P_OFF + (r + 8) * P_STRIDE + c + 1] = acc[mt][nt][3] * scale;
        }
    __syncthreads();

    // Row softmax: warp w handles rows w*16..w*16+15 (128 rows, 8 warps)
    #pragma unroll
    for (int rr = 0; rr < 16; rr++) {
        int row = wid * 16 + rr;
        float* pr = sm + P_OFF + row * P_STRIDE;
        float v[8];
        float mx = -1e30f;
        #pragma unroll
        for (int i = 0; i < 8; i++) { v[i] = pr[lane + 32 * i]; mx = fmaxf(mx, v[i]); }
        #pragma unroll
        for (int o = 16; o > 0; o >>= 1) mx = fmaxf(mx, __shfl_xor_sync(~0u, mx, o));
        float s = 0.f;
        #pragma unroll
        for (int i = 0; i < 8; i++) { v[i] = __expf(v[i] - mx); s += v[i]; }
        #pragma unroll
        for (int o = 16; o > 0; o >>= 1) s += __shfl_xor_sync(~0u, s, o);
        float inv = 1.f / s;
        #pragma unroll
        for (int i = 0; i < 8; i++)
            pr[lane + 32 * i] = __uint_as_float(f2tf32(v[i] * inv));
    }
    __syncthreads();

    // ============ Phase 3: out = P V (128 x 768), 4 d-chunks of 192, V in 32-row slabs ============
    for (int ch = 0; ch < 4; ch++) {
        const int d0 = ch * DCH;

        // Warp tile: 64 rows x 48 cols -> mt 0..3, nt 0..5
        float o[4][6][4];
        #pragma unroll
        for (int mt = 0; mt < 4; mt++)
            #pragma unroll
            for (int nt = 0; nt < 6; nt++)
                #pragma unroll
                for (int i = 0; i < 4; i++)
                    o[mt][nt][i] = 0.f;

        // Prologue: slab 0 -> V buf0 (32 rows x 192 cols)
        #pragma unroll
        for (int j = 0; j < 6; j++) {
            int idx = j * THREADS + tid;
            int row = idx / 48, c4 = idx % 48;
            float4 v = *(const float4*)(x + (size_t)(segbase + 2 * row) * DIM + d0 + c4 * 4);
            sts_tf32x4(sm + V_OFF + row * V_STRIDE + c4 * 4, v);
        }
        __syncthreads();

        float4 vst[6];
        for (int sl = 0; sl < NSLAB; sl++) {
            const uint32_t* vcur = smu + V_OFF + (sl & 1) * VSLABF;
            const bool pf = (sl + 1 < NSLAB);
            if (pf) {
                const int rbase = (sl + 1) * KSLAB;
                #pragma unroll
                for (int j = 0; j < 6; j++) {
                    int idx = j * THREADS + tid;
                    int row = idx / 48, c4 = idx % 48;
                    vst[j] = *(const float4*)(x + (size_t)(segbase + 2 * (rbase + row)) * DIM + d0 + c4 * 4);
                }
            }
            const uint32_t* abase0 = smu + P_OFF + (wm * 64 + ln4) * P_STRIDE + sl * KSLAB + lc4;
            const uint32_t* bbase0 = vcur + lc4 * V_STRIDE + wn * 48 + ln4;
            #pragma unroll
            for (int ks = 0; ks < KSLAB / 8; ks++) {
                const int kk = ks * 8;
                uint32_t a[4][4];
                #pragma unroll
                for (int mt = 0; mt < 4; mt++) {
                    const uint32_t* ba = abase0 + mt * 16 * P_STRIDE + kk;
                    a[mt][0] = ba[0];
                    a[mt][1] = ba[8 * P_STRIDE];
                    a[mt][2] = ba[4];
                    a[mt][3] = ba[8 * P_STRIDE + 4];
                }
                const uint32_t* bb0 = bbase0 + kk * V_STRIDE;
                #pragma unroll
                for (int nt = 0; nt < 6; nt++) {
                    const uint32_t* bb = bb0 + nt * 8;
                    uint32_t bf[2] = { bb[0], bb[4 * V_STRIDE] };
                    #pragma unroll
                    for (int mt = 0; mt < 4; mt++)
                        mma8(o[mt][nt], a[mt], bf);
                }
            }
            if (pf) {
                float* dst = sm + V_OFF + ((sl + 1) & 1) * VSLABF;
                #pragma unroll
                for (int j = 0; j < 6; j++) {
                    int idx = j * THREADS + tid;
                    int row = idx / 48, c4 = idx % 48;
                    sts_tf32x4(dst + row * V_STRIDE + c4 * 4, vst[j]);
                }
            }
            __syncthreads();
        }

        // Epilogue: even (gathered) rows get results
        #pragma unroll
        for (int mt = 0; mt < 4; mt++)
            #pragma unroll
            for (int nt = 0; nt < 6; nt++) {
                int gr = m0 + wm * 64 + mt * 16 + ln4;
                int c  = d0 + wn * 48 + nt * 8 + 2 * lc4;
                long tok0 = segbase + 2 * (long)gr;
                long tok1 = segbase + 2 * (long)(gr + 8);
                *(float2*)(y + (size_t)tok0 * DIM + c) = make_float2(o[mt][nt][0], o[mt][nt][1]);
                *(float2*)(y + (size_t)tok1 * DIM + c) = make_float2(o[mt][nt][2], o[mt][nt][3]);
            }

        // Odd partner rows are exactly zero (this d-chunk)
        #pragma unroll
        for (int j = 0; j < 24; j++) {
            int i = j * THREADS + tid;
            int r = i / 48, c4 = i % 48;
            long tok = segbase + 2 * (long)(m0 + r) + 1;
            *(float4*)(y + (size_t)tok * DIM + d0 + c4 * 4) = make_float4(0.f, 0.f, 0.f, 0.f);
        }
        __syncthreads();
    }
}

extern "C" void kernel_launch(void* const* d_in, const int* in_sizes, int n_in,
                              void* d_out, int out_size)
{
    const float* x = (const float*)d_in[0];
    float* y = (float*)d_out;
    cudaFuncSetAttribute(dilated_attn_kernel,
                         cudaFuncAttributeMaxDynamicSharedMemorySize, SMEM_BYTES);
    dilated_attn_kernel<<<BATCH * NSEG * 2, THREADS, SMEM_BYTES>>>(x, y);
}

// round 10
// speedup vs baseline: 1.2631x; 1.0659x over previous
#include <cuda_runtime.h>
#include <cstdint>

// Problem constants (fixed by reference)
#define BATCH   4
#define NTOK    8192
#define DIM     768
#define SEGW    512
#define NSEG    16
#define MG      256       // gathered (even) rows per segment
#define TM      128       // Q rows per CTA tile
#define KC      32        // phase-1 k-chunk width
#define NCHUNK  (DIM/KC)  // 24
#define THREADS 256

#define DCH     192       // phase-3 d chunk width
#define KSLAB   32        // phase-3 V slab rows
#define NSLAB   (MG/KSLAB)// 8

// Padded smem strides (floats). k-major: stride%8==4; V n-major: stride%32==8.
#define K_STRIDE 36
#define P_STRIDE 260
#define V_STRIDE 200      // 192 + 8

#define KCHF    (MG*K_STRIDE)     // 9216 floats per K buffer (2 buffers alias P)
#define KCHB    (KCHF*4)          // 36864 bytes
#define P_OFF   0
#define P_FLOATS (TM*P_STRIDE)    // 33280
#define V_OFF   P_FLOATS
#define V_OFFB  (V_OFF*4)         // 133120 bytes
#define VSLABF  (KSLAB*V_STRIDE)  // 6400
#define VSLABB  (VSLABF*4)        // 25600 bytes
#define SMEM_FLOATS (V_OFF + 2*VSLABF)   // 46080
#define SMEM_BYTES  (SMEM_FLOATS * 4)    // 184320  (1 CTA/SM)

__device__ __forceinline__ uint32_t smem_u32(const void* p) {
    uint32_t a;
    asm("{ .reg .u64 t; cvta.to.shared.u64 t, %1; cvt.u32.u64 %0, t; }" : "=r"(a) : "l"(p));
    return a;
}
__device__ __forceinline__ void cp16(uint32_t dst, const float* src) {
    asm volatile("cp.async.cg.shared.global [%0], [%1], 16;" :: "r"(dst), "l"(src) : "memory");
}
#define CP_COMMIT() asm volatile("cp.async.commit_group;" ::: "memory")
#define CP_WAIT(n)  asm volatile("cp.async.wait_group %0;" :: "n"(n) : "memory")

__device__ __forceinline__ void mma8(float c[4], const uint32_t a[4], const uint32_t b[2]) {
    asm volatile(
        "mma.sync.aligned.m16n8k8.row.col.f32.tf32.tf32.f32 "
        "{%0,%1,%2,%3}, {%4,%5,%6,%7}, {%8,%9}, {%0,%1,%2,%3};\n"
        : "+f"(c[0]), "+f"(c[1]), "+f"(c[2]), "+f"(c[3])
        : "r"(a[0]), "r"(a[1]), "r"(a[2]), "r"(a[3]), "r"(b[0]), "r"(b[1]));
}

__global__ __launch_bounds__(THREADS, 1)
void dilated_attn_kernel(const float* __restrict__ x, float* __restrict__ y)
{
    extern __shared__ float sm[];
    uint32_t* smu = (uint32_t*)sm;
    const uint32_t sb = smem_u32(sm);
    const int tid  = threadIdx.x;
    const int lane = tid & 31;
    const int wid  = tid >> 5;     // 0..7

    const int mtile = blockIdx.x & 1;       // 2 x 128-row tiles per problem
    const int pid   = blockIdx.x >> 1;      // 64 problems
    const long segbase = (long)(pid >> 4) * NTOK + (long)(pid & 15) * SEGW;
    const int  m0 = mtile * TM;

    // Warp layout (both GEMMs): 2 m-warps x 4 n-warps, 64-row warp tiles
    const int wm  = wid & 1;
    const int wn  = wid >> 1;
    const int ln4 = lane >> 2;   // fragment group 0..7
    const int lc4 = lane & 3;    // thread-in-group 0..3

    // Per-thread fill coords (phase 1): 2048 float4 items / 256 thr = 8 each
    const int fr  = tid >> 3;          // base row  (x8 over j via +32*... no: idx=j*256+tid)
    // (computed inline below)

    // ============ Phase 1: S = Q K^T (128 x 256), cp.async double-buffered K chunks ====
    float acc[4][8][4];
    #pragma unroll
    for (int mt = 0; mt < 4; mt++)
        #pragma unroll
        for (int nt = 0; nt < 8; nt++)
            #pragma unroll
            for (int i = 0; i < 4; i++)
                acc[mt][nt][i] = 0.f;

    // Prologue: chunk 0 -> buf0
    #pragma unroll
    for (int j = 0; j < 8; j++) {
        int idx = j * THREADS + tid;
        int r = idx >> 3, c4 = idx & 7;
        cp16(sb + (uint32_t)(r * 144 + c4 * 16),
             x + (size_t)(segbase + 2 * r) * DIM + c4 * 4);
    }
    CP_COMMIT();

    for (int kc = 0; kc < NCHUNK; kc++) {
        const bool pf = (kc + 1 < NCHUNK);
        __syncthreads();                       // all mma(kc-1) done -> safe to refill nb
        if (pf) {
            const int kd = (kc + 1) * KC;
            const uint32_t nbb = (kc & 1) ? 0u : (uint32_t)KCHB;
            #pragma unroll
            for (int j = 0; j < 8; j++) {
                int idx = j * THREADS + tid;
                int r = idx >> 3, c4 = idx & 7;
                cp16(sb + nbb + (uint32_t)(r * 144 + c4 * 16),
                     x + (size_t)(segbase + 2 * r) * DIM + kd + c4 * 4);
            }
            CP_COMMIT();
            CP_WAIT(1);                        // chunk kc's group done (ours)
        } else {
            CP_WAIT(0);
        }
        __syncthreads();                       // everyone's chunk kc copies visible

        const uint32_t* cur = smu + ((kc & 1) ? KCHF : 0);
        const uint32_t* abase = cur + (m0 + wm * 64 + ln4) * K_STRIDE + lc4;
        const uint32_t* bbase = cur + (wn * 64 + ln4) * K_STRIDE + lc4;
        #pragma unroll
        for (int ks = 0; ks < KC / 8; ks++) {
            const int kk = ks * 8;
            uint32_t a[4][4];
            #pragma unroll
            for (int mt = 0; mt < 4; mt++) {
                const uint32_t* ba = abase + mt * 16 * K_STRIDE + kk;
                a[mt][0] = ba[0];
                a[mt][1] = ba[8 * K_STRIDE];
                a[mt][2] = ba[4];
                a[mt][3] = ba[8 * K_STRIDE + 4];
            }
            #pragma unroll
            for (int nt = 0; nt < 8; nt++) {
                const uint32_t* bb = bbase + nt * 8 * K_STRIDE + kk;
                uint32_t bf[2] = { bb[0], bb[4] };
                #pragma unroll
                for (int mt = 0; mt < 4; mt++)
                    mma8(acc[mt][nt], a[mt], bf);
            }
        }
    }
    __syncthreads();   // all K-buffer reads done; P aliases them

    // ============ Phase 2: scale + softmax into P (raw fp32; mma truncates to tf32) ====
    const float scale = 0.03608439182435161f;  // 768^-0.5
    #pragma unroll
    for (int mt = 0; mt < 4; mt++)
        #pragma unroll
        for (int nt = 0; nt < 8; nt++) {
            int r = wm * 64 + mt * 16 + ln4;
            int c = wn * 64 + nt * 8 + 2 * lc4;
            sm[P_OFF + r * P_STRIDE + c]           = acc[mt][nt][0] * scale;
            sm[P_OFF + r * P_STRIDE + c + 1]       = acc[mt][nt][1] * scale;
            sm[P_OFF + (r + 8) * P_STRIDE + c]     = acc[mt][nt][2] * scale;
            sm[P_OFF + (r + 8) * P_STRIDE + c + 1] = acc[mt][nt][3] * scale;
        }
    __syncthreads();

    // Row softmax: warp w handles rows w*16..w*16+15
    #pragma unroll
    for (int rr = 0; rr < 16; rr++) {
        int row = wid * 16 + rr;
        float* pr = sm + P_OFF + row * P_STRIDE;
        float v[8];
        float mx = -1e30f;
        #pragma unroll
        for (int i = 0; i < 8; i++) { v[i] = pr[lane + 32 * i]; mx = fmaxf(mx, v[i]); }
        #pragma unroll
        for (int o = 16; o > 0; o >>= 1) mx = fmaxf(mx, __shfl_xor_sync(~0u, mx, o));
        float s = 0.f;
        #pragma unroll
        for (int i = 0; i < 8; i++) { v[i] = __expf(v[i] - mx); s += v[i]; }
        #pragma unroll
        for (int o = 16; o > 0; o >>= 1) s += __shfl_xor_sync(~0u, s, o);
        float inv = 1.f / s;
        #pragma unroll
        for (int i = 0; i < 8; i++) pr[lane + 32 * i] = v[i] * inv;
    }
    __syncthreads();

    // ============ Phase 3: out = P V (128 x 768), 4 d-chunks, cp.async V slabs ============
    for (int ch = 0; ch < 4; ch++) {
        const int d0 = ch * DCH;

        float o[4][6][4];
        #pragma unroll
        for (int mt = 0; mt < 4; mt++)
            #pragma unroll
            for (int nt = 0; nt < 6; nt++)
                #pragma unroll
                for (int i = 0; i < 4; i++)
                    o[mt][nt][i] = 0.f;

        // Prologue: slab 0 -> V buf0 (32 rows x 192 cols)
        #pragma unroll
        for (int j = 0; j < 6; j++) {
            int idx = j * THREADS + tid;
            int row = idx / 48, c4 = idx % 48;
            cp16(sb + V_OFFB + (uint32_t)(row * 800 + c4 * 16),
                 x + (size_t)(segbase + 2 * row) * DIM + d0 + c4 * 4);
        }
        CP_COMMIT();

        for (int sl = 0; sl < NSLAB; sl++) {
            const bool pf = (sl + 1 < NSLAB);
            __syncthreads();                   // all mma(sl-1) done
            if (pf) {
                const int rbase = (sl + 1) * KSLAB;
                const uint32_t nbb = V_OFFB + ((sl & 1) ? 0u : (uint32_t)VSLABB);
                #pragma unroll
                for (int j = 0; j < 6; j++) {
                    int idx = j * THREADS + tid;
                    int row = idx / 48, c4 = idx % 48;
                    cp16(sb + nbb + (uint32_t)(row * 800 + c4 * 16),
                         x + (size_t)(segbase + 2 * (rbase + row)) * DIM + d0 + c4 * 4);
                }
                CP_COMMIT();
                CP_WAIT(1);
            } else {
                CP_WAIT(0);
            }
            __syncthreads();

            const uint32_t* vcur = smu + V_OFF + (sl & 1) * VSLABF;
            const uint32_t* abase0 = smu + P_OFF + (wm * 64 + ln4) * P_STRIDE + sl * KSLAB + lc4;
            const uint32_t* bbase0 = vcur + lc4 * V_STRIDE + wn * 48 + ln4;
            #pragma unroll
            for (int ks = 0; ks < KSLAB / 8; ks++) {
                const int kk = ks * 8;
                uint32_t a[4][4];
                #pragma unroll
                for (int mt = 0; mt < 4; mt++) {
                    const uint32_t* ba = abase0 + mt * 16 * P_STRIDE + kk;
                    a[mt][0] = ba[0];
                    a[mt][1] = ba[8 * P_STRIDE];
                    a[mt][2] = ba[4];
                    a[mt][3] = ba[8 * P_STRIDE + 4];
                }
                const uint32_t* bb0 = bbase0 + kk * V_STRIDE;
                #pragma unroll
                for (int nt = 0; nt < 6; nt++) {
                    const uint32_t* bb = bb0 + nt * 8;
                    uint32_t bf[2] = { bb[0], bb[4 * V_STRIDE] };
                    #pragma unroll
                    for (int mt = 0; mt < 4; mt++)
                        mma8(o[mt][nt], a[mt], bf);
                }
            }
        }

        // Epilogue: even (gathered) rows get results
        #pragma unroll
        for (int mt = 0; mt < 4; mt++)
            #pragma unroll
            for (int nt = 0; nt < 6; nt++) {
                int gr = m0 + wm * 64 + mt * 16 + ln4;
                int c  = d0 + wn * 48 + nt * 8 + 2 * lc4;
                long tok0 = segbase + 2 * (long)gr;
                long tok1 = segbase + 2 * (long)(gr + 8);
                *(float2*)(y + (size_t)tok0 * DIM + c) = make_float2(o[mt][nt][0], o[mt][nt][1]);
                *(float2*)(y + (size_t)tok1 * DIM + c) = make_float2(o[mt][nt][2], o[mt][nt][3]);
            }

        // Odd partner rows are exactly zero (this d-chunk)
        #pragma unroll
        for (int j = 0; j < 24; j++) {
            int i = j * THREADS + tid;
            int r = i / 48, c4 = i % 48;
            long tok = segbase + 2 * (long)(m0 + r) + 1;
            *(float4*)(y + (size_t)tok * DIM + d0 + c4 * 4) = make_float4(0.f, 0.f, 0.f, 0.f);
        }
    }
}

extern "C" void kernel_launch(void* const* d_in, const int* in_sizes, int n_in,
                              void* d_out, int out_size)
{
    const float* x = (const float*)d_in[0];
    float* y = (float*)d_out;
    cudaFuncSetAttribute(dilated_attn_kernel,
                         cudaFuncAttributeMaxDynamicSharedMemorySize, SMEM_BYTES);
    dilated_attn_kernel<<<BATCH * NSEG * 2, THREADS, SMEM_BYTES>>>(x, y);
}

// round 11
// speedup vs baseline: 1.3420x; 1.0624x over previous
#include <cuda_runtime.h>
#include <cstdint>

// Problem constants (fixed by reference)
#define BATCH   4
#define NTOK    8192
#define DIM     768
#define SEGW    512
#define NSEG    16
#define MG      256       // gathered (even) rows per segment
#define TM      128       // Q rows per CTA tile
#define KC      32        // phase-1 k-chunk width
#define NCHUNK  (DIM/KC)  // 24
#define THREADS 256

#define DCH     192       // phase-3 d chunk width
#define KSLAB   32        // phase-3 V slab rows
#define NIT3    32        // 4 d-chunks x 8 slabs, flattened

// Padded smem strides (floats). k-major: stride%8==4; V n-major: stride%32==8.
#define K_STRIDE 36
#define P_STRIDE 260
#define V_STRIDE 200      // 192 + 8

#define KCHF    (MG*K_STRIDE)     // 9216 floats per K buffer (3 buffers alias P)
#define KCHB    (KCHF*4)          // 36864 bytes
#define P_OFF   0
#define P_FLOATS (TM*P_STRIDE)    // 33280 floats = 133120 B >= 3*KCHB
#define V_OFF   P_FLOATS
#define V_OFFB  (V_OFF*4)         // 133120 bytes
#define VSLABF  (KSLAB*V_STRIDE)  // 6400 floats
#define VSLABB  (VSLABF*4)        // 25600 bytes
#define SMEM_FLOATS (V_OFF + 3*VSLABF)   // 52480
#define SMEM_BYTES  (SMEM_FLOATS * 4)    // 209920  (1 CTA/SM)

__device__ __forceinline__ uint32_t smem_u32(const void* p) {
    uint32_t a;
    asm("{ .reg .u64 t; cvta.to.shared.u64 t, %1; cvt.u32.u64 %0, t; }" : "=r"(a) : "l"(p));
    return a;
}
__device__ __forceinline__ void cp16(uint32_t dst, const float* src) {
    asm volatile("cp.async.cg.shared.global [%0], [%1], 16;" :: "r"(dst), "l"(src) : "memory");
}
#define CP_COMMIT() asm volatile("cp.async.commit_group;" ::: "memory")
#define CP_WAIT(n)  asm volatile("cp.async.wait_group %0;" :: "n"(n) : "memory")

__device__ __forceinline__ void mma8(float c[4], const uint32_t a[4], const uint32_t b[2]) {
    asm volatile(
        "mma.sync.aligned.m16n8k8.row.col.f32.tf32.tf32.f32 "
        "{%0,%1,%2,%3}, {%4,%5,%6,%7}, {%8,%9}, {%0,%1,%2,%3};\n"
        : "+f"(c[0]), "+f"(c[1]), "+f"(c[2]), "+f"(c[3])
        : "r"(a[0]), "r"(a[1]), "r"(a[2]), "r"(a[3]), "r"(b[0]), "r"(b[1]));
}

__global__ __launch_bounds__(THREADS, 1)
void dilated_attn_kernel(const float* __restrict__ x, float* __restrict__ y)
{
    extern __shared__ float sm[];
    uint32_t* smu = (uint32_t*)sm;
    const uint32_t sb = smem_u32(sm);
    const int tid  = threadIdx.x;
    const int lane = tid & 31;
    const int wid  = tid >> 5;     // 0..7

    const int mtile = blockIdx.x & 1;       // 2 x 128-row tiles per problem
    const int pid   = blockIdx.x >> 1;      // 64 problems
    const long segbase = (long)(pid >> 4) * NTOK + (long)(pid & 15) * SEGW;
    const int  m0 = mtile * TM;

    // Warp layout (both GEMMs): 2 m-warps x 4 n-warps, 64-row warp tiles
    const int wm  = wid & 1;
    const int wn  = wid >> 1;
    const int ln4 = lane >> 2;   // fragment group 0..7
    const int lc4 = lane & 3;    // thread-in-group 0..3

    // ============ Phase 1: S = Q K^T (128 x 256), 3-stage cp.async K ring ============
    float acc[4][8][4];
    #pragma unroll
    for (int mt = 0; mt < 4; mt++)
        #pragma unroll
        for (int nt = 0; nt < 8; nt++)
            #pragma unroll
            for (int i = 0; i < 4; i++)
                acc[mt][nt][i] = 0.f;

    // Prologue: chunks 0,1 -> bufs 0,1
    #pragma unroll
    for (int c0 = 0; c0 < 2; c0++) {
        #pragma unroll
        for (int j = 0; j < 8; j++) {
            int idx = j * THREADS + tid;
            int r = idx >> 3, c4 = idx & 7;
            cp16(sb + (uint32_t)(c0 * KCHB + r * 144 + c4 * 16),
                 x + (size_t)(segbase + 2 * r) * DIM + c0 * KC + c4 * 4);
        }
        CP_COMMIT();
    }

    for (int kc = 0; kc < NCHUNK; kc++) {
        CP_WAIT(1);            // chunk kc landed (ours)
        __syncthreads();       // everyone's chunk kc visible + mma(kc-1) done by all
        // Fill chunk kc+2 into ring slot (kc+2)%3 (== (kc-1)%3, free after barrier)
        if (kc + 2 < NCHUNK) {
            const int kd = (kc + 2) * KC;
            const uint32_t nbb = (uint32_t)(((kc + 2) % 3) * KCHB);
            #pragma unroll
            for (int j = 0; j < 8; j++) {
                int idx = j * THREADS + tid;
                int r = idx >> 3, c4 = idx & 7;
                cp16(sb + nbb + (uint32_t)(r * 144 + c4 * 16),
                     x + (size_t)(segbase + 2 * r) * DIM + kd + c4 * 4);
            }
        }
        CP_COMMIT();           // empty group near tail keeps wait count uniform

        // Overlap: zero the odd partner output rows (4 float4/thread/iter, 24 iters)
        #pragma unroll
        for (int j = 0; j < 4; j++) {
            int i = (kc * 4 + j) * THREADS + tid;        // 0..24575
            int r = i / 192, c4 = i % 192;
            long tok = segbase + 2 * (long)(m0 + r) + 1;
            *(float4*)(y + (size_t)tok * DIM + c4 * 4) = make_float4(0.f, 0.f, 0.f, 0.f);
        }

        const uint32_t* cur = smu + (kc % 3) * KCHF;
        const uint32_t* abase = cur + (m0 + wm * 64 + ln4) * K_STRIDE + lc4;
        const uint32_t* bbase = cur + (wn * 64 + ln4) * K_STRIDE + lc4;
        #pragma unroll
        for (int ks = 0; ks < KC / 8; ks++) {
            const int kk = ks * 8;
            uint32_t a[4][4];
            #pragma unroll
            for (int mt = 0; mt < 4; mt++) {
                const uint32_t* ba = abase + mt * 16 * K_STRIDE + kk;
                a[mt][0] = ba[0];
                a[mt][1] = ba[8 * K_STRIDE];
                a[mt][2] = ba[4];
                a[mt][3] = ba[8 * K_STRIDE + 4];
            }
            #pragma unroll
            for (int nt = 0; nt < 8; nt++) {
                const uint32_t* bb = bbase + nt * 8 * K_STRIDE + kk;
                uint32_t bf[2] = { bb[0], bb[4] };
                #pragma unroll
                for (int mt = 0; mt < 4; mt++)
                    mma8(acc[mt][nt], a[mt], bf);
            }
        }
    }
    __syncthreads();   // all K-ring reads done; P aliases the ring

    // ============ Phase 2: scale + softmax into P (raw fp32; mma truncates to tf32) ====
    const float scale = 0.03608439182435161f;  // 768^-0.5
    #pragma unroll
    for (int mt = 0; mt < 4; mt++)
        #pragma unroll
        for (int nt = 0; nt < 8; nt++) {
            int r = wm * 64 + mt * 16 + ln4;
            int c = wn * 64 + nt * 8 + 2 * lc4;
            sm[P_OFF + r * P_STRIDE + c]           = acc[mt][nt][0] * scale;
            sm[P_OFF + r * P_STRIDE + c + 1]       = acc[mt][nt][1] * scale;
            sm[P_OFF + (r + 8) * P_STRIDE + c]     = acc[mt][nt][2] * scale;
            sm[P_OFF + (r + 8) * P_STRIDE + c + 1] = acc[mt][nt][3] * scale;
        }
    __syncthreads();

    // Row softmax: warp w handles rows w*16..w*16+15
    #pragma unroll
    for (int rr = 0; rr < 16; rr++) {
        int row = wid * 16 + rr;
        float* pr = sm + P_OFF + row * P_STRIDE;
        float v[8];
        float mx = -1e30f;
        #pragma unroll
        for (int i = 0; i < 8; i++) { v[i] = pr[lane + 32 * i]; mx = fmaxf(mx, v[i]); }
        #pragma unroll
        for (int o = 16; o > 0; o >>= 1) mx = fmaxf(mx, __shfl_xor_sync(~0u, mx, o));
        float s = 0.f;
        #pragma unroll
        for (int i = 0; i < 8; i++) { v[i] = __expf(v[i] - mx); s += v[i]; }
        #pragma unroll
        for (int o = 16; o > 0; o >>= 1) s += __shfl_xor_sync(~0u, s, o);
        float inv = 1.f / s;
        #pragma unroll
        for (int i = 0; i < 8; i++) pr[lane + 32 * i] = v[i] * inv;
    }
    __syncthreads();

    // ============ Phase 3: out = P V (128 x 768), flattened (ch,sl) pipeline ============
    // V fill for flattened step t: slab rows (t&7)*32..+31, d-cols (t>>3)*192..+191
    // Prologue: t = 0, 1 -> vbufs 0, 1
    #pragma unroll
    for (int t0 = 0; t0 < 2; t0++) {
        const int rb = (t0 & 7) * KSLAB;
        const int dd = (t0 >> 3) * DCH;
        #pragma unroll
        for (int j = 0; j < 6; j++) {
            int idx = j * THREADS + tid;
            int row = idx / 48, c4 = idx % 48;
            cp16(sb + V_OFFB + (uint32_t)(t0 * VSLABB + row * 800 + c4 * 16),
                 x + (size_t)(segbase + 2 * (rb + row)) * DIM + dd + c4 * 4);
        }
        CP_COMMIT();
    }

    float o[4][6][4];
    #pragma unroll
    for (int mt = 0; mt < 4; mt++)
        #pragma unroll
        for (int nt = 0; nt < 6; nt++)
            #pragma unroll
            for (int i = 0; i < 4; i++)
                o[mt][nt][i] = 0.f;

    for (int t = 0; t < NIT3; t++) {
        const int sl = t & 7;
        const int d0 = (t >> 3) * DCH;

        CP_WAIT(1);
        __syncthreads();
        if (t + 2 < NIT3) {
            const int t2 = t + 2;
            const int rb = (t2 & 7) * KSLAB;
            const int dd = (t2 >> 3) * DCH;
            const uint32_t nbb = V_OFFB + (uint32_t)((t2 % 3) * VSLABB);
            #pragma unroll
            for (int j = 0; j < 6; j++) {
                int idx = j * THREADS + tid;
                int row = idx / 48, c4 = idx % 48;
                cp16(sb + nbb + (uint32_t)(row * 800 + c4 * 16),
                     x + (size_t)(segbase + 2 * (rb + row)) * DIM + dd + c4 * 4);
            }
        }
        CP_COMMIT();

        const uint32_t* vcur = smu + V_OFF + (t % 3) * VSLABF;
        const uint32_t* abase0 = smu + P_OFF + (wm * 64 + ln4) * P_STRIDE + sl * KSLAB + lc4;
        const uint32_t* bbase0 = vcur + lc4 * V_STRIDE + wn * 48 + ln4;
        #pragma unroll
        for (int ks = 0; ks < KSLAB / 8; ks++) {
            const int kk = ks * 8;
            uint32_t a[4][4];
            #pragma unroll
            for (int mt = 0; mt < 4; mt++) {
                const uint32_t* ba = abase0 + mt * 16 * P_STRIDE + kk;
                a[mt][0] = ba[0];
                a[mt][1] = ba[8 * P_STRIDE];
                a[mt][2] = ba[4];
                a[mt][3] = ba[8 * P_STRIDE + 4];
            }
            const uint32_t* bb0 = bbase0 + kk * V_STRIDE;
            #pragma unroll
            for (int nt = 0; nt < 6; nt++) {
                const uint32_t* bb = bb0 + nt * 8;
                uint32_t bf[2] = { bb[0], bb[4 * V_STRIDE] };
                #pragma unroll
                for (int mt = 0; mt < 4; mt++)
                    mma8(o[mt][nt], a[mt], bf);
            }
        }

        if (sl == 7) {
            // Epilogue for this d-chunk: even (gathered) rows get results
            #pragma unroll
            for (int mt = 0; mt < 4; mt++)
                #pragma unroll
                for (int nt = 0; nt < 6; nt++) {
                    int gr = m0 + wm * 64 + mt * 16 + ln4;
                    int c  = d0 + wn * 48 + nt * 8 + 2 * lc4;
                    long tok0 = segbase + 2 * (long)gr;
                    long tok1 = segbase + 2 * (long)(gr + 8);
                    *(float2*)(y + (size_t)tok0 * DIM + c) = make_float2(o[mt][nt][0], o[mt][nt][1]);
                    *(float2*)(y + (size_t)tok1 * DIM + c) = make_float2(o[mt][nt][2], o[mt][nt][3]);
                    #pragma unroll
                    for (int i = 0; i < 4; i++) o[mt][nt][i] = 0.f;
                }
        }
    }
}

extern "C" void kernel_launch(void* const* d_in, const int* in_sizes, int n_in,
                              void* d_out, int out_size)
{
    const float* x = (const float*)d_in[0];
    float* y = (float*)d_out;
    cudaFuncSetAttribute(dilated_attn_kernel,
                         cudaFuncAttributeMaxDynamicSharedMemorySize, SMEM_BYTES);
    dilated_attn_kernel<<<BATCH * NSEG * 2, THREADS, SMEM_BYTES>>>(x, y);
}

// round 12
// speedup vs baseline: 1.3716x; 1.0220x over previous
#include <cuda_runtime.h>
#include <cstdint>

// Problem constants (fixed by reference)
#define BATCH   4
#define NTOK    8192
#define DIM     768
#define SEGW    512
#define NSEG    16
#define MG      256       // gathered (even) rows per segment
#define TM      128       // Q rows per CTA tile
#define KC      32        // phase-1 k-chunk width
#define NCHUNK  (DIM/KC)  // 24
#define THREADS 256

#define DCH     192       // phase-3 d chunk width
#define KSLAB   32        // phase-3 V slab rows
#define NIT3    32        // 4 d-chunks x 8 slabs, flattened

// Padded smem strides (floats). k-major: stride%8==4; V n-major: stride%32==8.
#define K_STRIDE 36
#define P_STRIDE 260
#define V_STRIDE 200      // 192 + 8

#define KCHF    (MG*K_STRIDE)     // 9216 floats per K buffer (3 buffers alias P)
#define KCHB    (KCHF*4)          // 36864 bytes
#define P_OFF   0
#define P_FLOATS (TM*P_STRIDE)    // 33280 floats = 133120 B >= 3*KCHB
#define V_OFF   P_FLOATS
#define V_OFFB  (V_OFF*4)         // 133120 bytes
#define VSLABF  (KSLAB*V_STRIDE)  // 6400 floats
#define VSLABB  (VSLABF*4)        // 25600 bytes
#define SMEM_FLOATS (V_OFF + 3*VSLABF)   // 52480
#define SMEM_BYTES  (SMEM_FLOATS * 4)    // 209920  (1 CTA/SM)

__device__ __forceinline__ uint32_t smem_u32(const void* p) {
    uint32_t a;
    asm("{ .reg .u64 t; cvta.to.shared.u64 t, %1; cvt.u32.u64 %0, t; }" : "=r"(a) : "l"(p));
    return a;
}
__device__ __forceinline__ void cp16(uint32_t dst, const float* src) {
    asm volatile("cp.async.cg.shared.global [%0], [%1], 16;" :: "r"(dst), "l"(src) : "memory");
}
#define CP_COMMIT() asm volatile("cp.async.commit_group;" ::: "memory")
#define CP_WAIT(n)  asm volatile("cp.async.wait_group %0;" :: "n"(n) : "memory")

__device__ __forceinline__ void mma8(float c[4], const uint32_t a[4], const uint32_t b[2]) {
    asm volatile(
        "mma.sync.aligned.m16n8k8.row.col.f32.tf32.tf32.f32 "
        "{%0,%1,%2,%3}, {%4,%5,%6,%7}, {%8,%9}, {%0,%1,%2,%3};\n"
        : "+f"(c[0]), "+f"(c[1]), "+f"(c[2]), "+f"(c[3])
        : "r"(a[0]), "r"(a[1]), "r"(a[2]), "r"(a[3]), "r"(b[0]), "r"(b[1]));
}

__global__ __launch_bounds__(THREADS, 1)
void dilated_attn_kernel(const float* __restrict__ x, float* __restrict__ y)
{
    extern __shared__ float sm[];
    uint32_t* smu = (uint32_t*)sm;
    const uint32_t sb = smem_u32(sm);
    const int tid  = threadIdx.x;
    const int lane = tid & 31;
    const int wid  = tid >> 5;     // 0..7

    const int mtile = blockIdx.x & 1;       // 2 x 128-row tiles per problem
    const int pid   = blockIdx.x >> 1;      // 64 problems
    const long segbase = (long)(pid >> 4) * NTOK + (long)(pid & 15) * SEGW;
    const int  m0 = mtile * TM;

    // Warp layout (both GEMMs): 2 m-warps x 4 n-warps, 64-row warp tiles
    const int wm  = wid & 1;
    const int wn  = wid >> 1;
    const int ln4 = lane >> 2;   // fragment group 0..7
    const int lc4 = lane & 3;    // thread-in-group 0..3

    // ============ Phase 1: S = Q K^T (128 x 256), 3-stage cp.async K ring ============
    float acc[4][8][4];
    #pragma unroll
    for (int mt = 0; mt < 4; mt++)
        #pragma unroll
        for (int nt = 0; nt < 8; nt++)
            #pragma unroll
            for (int i = 0; i < 4; i++)
                acc[mt][nt][i] = 0.f;

    // Prologue: chunks 0,1 -> bufs 0,1
    #pragma unroll
    for (int c0 = 0; c0 < 2; c0++) {
        #pragma unroll
        for (int j = 0; j < 8; j++) {
            int idx = j * THREADS + tid;
            int r = idx >> 3, c4 = idx & 7;
            cp16(sb + (uint32_t)(c0 * KCHB + r * 144 + c4 * 16),
                 x + (size_t)(segbase + 2 * r) * DIM + c0 * KC + c4 * 4);
        }
        CP_COMMIT();
    }

    for (int kc = 0; kc < NCHUNK; kc++) {
        CP_WAIT(1);            // chunk kc landed (ours)
        __syncthreads();       // everyone's chunk kc visible + mma(kc-1) done by all
        // Fill chunk kc+2 into ring slot (kc+2)%3 (== (kc-1)%3, free after barrier)
        if (kc + 2 < NCHUNK) {
            const int kd = (kc + 2) * KC;
            const uint32_t nbb = (uint32_t)(((kc + 2) % 3) * KCHB);
            #pragma unroll
            for (int j = 0; j < 8; j++) {
                int idx = j * THREADS + tid;
                int r = idx >> 3, c4 = idx & 7;
                cp16(sb + nbb + (uint32_t)(r * 144 + c4 * 16),
                     x + (size_t)(segbase + 2 * r) * DIM + kd + c4 * 4);
            }
        }
        CP_COMMIT();           // empty group near tail keeps wait count uniform

        // Overlap: zero the odd partner output rows (4 float4/thread/iter, 24 iters)
        #pragma unroll
        for (int j = 0; j < 4; j++) {
            int i = (kc * 4 + j) * THREADS + tid;        // 0..24575
            int r = i / 192, c4 = i % 192;
            long tok = segbase + 2 * (long)(m0 + r) + 1;
            *(float4*)(y + (size_t)tok * DIM + c4 * 4) = make_float4(0.f, 0.f, 0.f, 0.f);
        }

        const uint32_t* cur = smu + (kc % 3) * KCHF;
        const uint32_t* abase = cur + (m0 + wm * 64 + ln4) * K_STRIDE + lc4;
        const uint32_t* bbase = cur + (wn * 64 + ln4) * K_STRIDE + lc4;

        // Explicit fragment double-buffer over the 4 k-steps
        uint32_t aF[2][4][4], bF[2][8][2];
        #pragma unroll
        for (int mt = 0; mt < 4; mt++) {
            const uint32_t* ba = abase + mt * 16 * K_STRIDE;
            aF[0][mt][0] = ba[0];
            aF[0][mt][1] = ba[8 * K_STRIDE];
            aF[0][mt][2] = ba[4];
            aF[0][mt][3] = ba[8 * K_STRIDE + 4];
        }
        #pragma unroll
        for (int nt = 0; nt < 8; nt++) {
            const uint32_t* bb = bbase + nt * 8 * K_STRIDE;
            bF[0][nt][0] = bb[0];
            bF[0][nt][1] = bb[4];
        }
        #pragma unroll
        for (int ks = 0; ks < KC / 8; ks++) {
            const int cs = ks & 1, nx = cs ^ 1;
            if (ks + 1 < KC / 8) {
                const int kk = (ks + 1) * 8;
                #pragma unroll
                for (int mt = 0; mt < 4; mt++) {
                    const uint32_t* ba = abase + mt * 16 * K_STRIDE + kk;
                    aF[nx][mt][0] = ba[0];
                    aF[nx][mt][1] = ba[8 * K_STRIDE];
                    aF[nx][mt][2] = ba[4];
                    aF[nx][mt][3] = ba[8 * K_STRIDE + 4];
                }
                #pragma unroll
                for (int nt = 0; nt < 8; nt++) {
                    const uint32_t* bb = bbase + nt * 8 * K_STRIDE + kk;
                    bF[nx][nt][0] = bb[0];
                    bF[nx][nt][1] = bb[4];
                }
            }
            #pragma unroll
            for (int nt = 0; nt < 8; nt++)
                #pragma unroll
                for (int mt = 0; mt < 4; mt++)
                    mma8(acc[mt][nt], aF[cs][mt], bF[cs][nt]);
        }
    }
    __syncthreads();   // all K-ring reads done; P aliases the ring

    // Prefetch phase-3 V tiles t=0,1 now; fills land under the softmax.
    #pragma unroll
    for (int t0 = 0; t0 < 2; t0++) {
        const int rb = (t0 & 7) * KSLAB;
        const int dd = (t0 >> 3) * DCH;
        #pragma unroll
        for (int j = 0; j < 6; j++) {
            int idx = j * THREADS + tid;
            int row = idx / 48, c4 = idx % 48;
            cp16(sb + V_OFFB + (uint32_t)(t0 * VSLABB + row * 800 + c4 * 16),
                 x + (size_t)(segbase + 2 * (rb + row)) * DIM + dd + c4 * 4);
        }
        CP_COMMIT();
    }

    // ============ Phase 2: scale + softmax into P (raw fp32; mma truncates to tf32) ====
    const float scale = 0.03608439182435161f;  // 768^-0.5
    #pragma unroll
    for (int mt = 0; mt < 4; mt++)
        #pragma unroll
        for (int nt = 0; nt < 8; nt++) {
            int r = wm * 64 + mt * 16 + ln4;
            int c = wn * 64 + nt * 8 + 2 * lc4;
            sm[P_OFF + r * P_STRIDE + c]           = acc[mt][nt][0] * scale;
            sm[P_OFF + r * P_STRIDE + c + 1]       = acc[mt][nt][1] * scale;
            sm[P_OFF + (r + 8) * P_STRIDE + c]     = acc[mt][nt][2] * scale;
            sm[P_OFF + (r + 8) * P_STRIDE + c + 1] = acc[mt][nt][3] * scale;
        }
    __syncthreads();

    // Row softmax: warp w handles rows w*16..w*16+15
    #pragma unroll
    for (int rr = 0; rr < 16; rr++) {
        int row = wid * 16 + rr;
        float* pr = sm + P_OFF + row * P_STRIDE;
        float v[8];
        float mx = -1e30f;
        #pragma unroll
        for (int i = 0; i < 8; i++) { v[i] = pr[lane + 32 * i]; mx = fmaxf(mx, v[i]); }
        #pragma unroll
        for (int o = 16; o > 0; o >>= 1) mx = fmaxf(mx, __shfl_xor_sync(~0u, mx, o));
        float s = 0.f;
        #pragma unroll
        for (int i = 0; i < 8; i++) { v[i] = __expf(v[i] - mx); s += v[i]; }
        #pragma unroll
        for (int o = 16; o > 0; o >>= 1) s += __shfl_xor_sync(~0u, s, o);
        float inv = 1.f / s;
        #pragma unroll
        for (int i = 0; i < 8; i++) pr[lane + 32 * i] = v[i] * inv;
    }
    __syncthreads();

    // ============ Phase 3: out = P V (128 x 768), flattened (ch,sl) pipeline ============
    float o[4][6][4];
    #pragma unroll
    for (int mt = 0; mt < 4; mt++)
        #pragma unroll
        for (int nt = 0; nt < 6; nt++)
            #pragma unroll
            for (int i = 0; i < 4; i++)
                o[mt][nt][i] = 0.f;

    for (int t = 0; t < NIT3; t++) {
        const int sl = t & 7;
        const int d0 = (t >> 3) * DCH;

        CP_WAIT(1);
        __syncthreads();
        if (t + 2 < NIT3) {
            const int t2 = t + 2;
            const int rb = (t2 & 7) * KSLAB;
            const int dd = (t2 >> 3) * DCH;
            const uint32_t nbb = V_OFFB + (uint32_t)((t2 % 3) * VSLABB);
            #pragma unroll
            for (int j = 0; j < 6; j++) {
                int idx = j * THREADS + tid;
                int row = idx / 48, c4 = idx % 48;
                cp16(sb + nbb + (uint32_t)(row * 800 + c4 * 16),
                     x + (size_t)(segbase + 2 * (rb + row)) * DIM + dd + c4 * 4);
            }
        }
        CP_COMMIT();

        const uint32_t* vcur = smu + V_OFF + (t % 3) * VSLABF;
        const uint32_t* abase0 = smu + P_OFF + (wm * 64 + ln4) * P_STRIDE + sl * KSLAB + lc4;
        const uint32_t* bbase0 = vcur + lc4 * V_STRIDE + wn * 48 + ln4;

        // Explicit fragment double-buffer over the 4 k-steps
        uint32_t aF[2][4][4], bF[2][6][2];
        #pragma unroll
        for (int mt = 0; mt < 4; mt++) {
            const uint32_t* ba = abase0 + mt * 16 * P_STRIDE;
            aF[0][mt][0] = ba[0];
            aF[0][mt][1] = ba[8 * P_STRIDE];
            aF[0][mt][2] = ba[4];
            aF[0][mt][3] = ba[8 * P_STRIDE + 4];
        }
        #pragma unroll
        for (int nt = 0; nt < 6; nt++) {
            const uint32_t* bb = bbase0 + nt * 8;
            bF[0][nt][0] = bb[0];
            bF[0][nt][1] = bb[4 * V_STRIDE];
        }
        #pragma unroll
        for (int ks = 0; ks < KSLAB / 8; ks++) {
            const int cs = ks & 1, nx = cs ^ 1;
            if (ks + 1 < KSLAB / 8) {
                const int kk = (ks + 1) * 8;
                #pragma unroll
                for (int mt = 0; mt < 4; mt++) {
                    const uint32_t* ba = abase0 + mt * 16 * P_STRIDE + kk;
                    aF[nx][mt][0] = ba[0];
                    aF[nx][mt][1] = ba[8 * P_STRIDE];
                    aF[nx][mt][2] = ba[4];
                    aF[nx][mt][3] = ba[8 * P_STRIDE + 4];
                }
                #pragma unroll
                for (int nt = 0; nt < 6; nt++) {
                    const uint32_t* bb = bbase0 + kk * V_STRIDE + nt * 8;
                    bF[nx][nt][0] = bb[0];
                    bF[nx][nt][1] = bb[4 * V_STRIDE];
                }
            }
            #pragma unroll
            for (int nt = 0; nt < 6; nt++)
                #pragma unroll
                for (int mt = 0; mt < 4; mt++)
                    mma8(o[mt][nt], aF[cs][mt], bF[cs][nt]);
        }

        if (sl == 7) {
            // Epilogue for this d-chunk: even (gathered) rows get results
            #pragma unroll
            for (int mt = 0; mt < 4; mt++)
                #pragma unroll
                for (int nt = 0; nt < 6; nt++) {
                    int gr = m0 + wm * 64 + mt * 16 + ln4;
                    int c  = d0 + wn * 48 + nt * 8 + 2 * lc4;
                    long tok0 = segbase + 2 * (long)gr;
                    long tok1 = segbase + 2 * (long)(gr + 8);
                    *(float2*)(y + (size_t)tok0 * DIM + c) = make_float2(o[mt][nt][0], o[mt][nt][1]);
                    *(float2*)(y + (size_t)tok1 * DIM + c) = make_float2(o[mt][nt][2], o[mt][nt][3]);
                    #pragma unroll
                    for (int i = 0; i < 4; i++) o[mt][nt][i] = 0.f;
                }
        }
    }
}

extern "C" void kernel_launch(void* const* d_in, const int* in_sizes, int n_in,
                              void* d_out, int out_size)
{
    const float* x = (const float*)d_in[0];
    float* y = (float*)d_out;
    cudaFuncSetAttribute(dilated_attn_kernel,
                         cudaFuncAttributeMaxDynamicSharedMemorySize, SMEM_BYTES);
    dilated_attn_kernel<<<BATCH * NSEG * 2, THREADS, SMEM_BYTES>>>(x, y);
}

// round 13
// speedup vs baseline: 1.4043x; 1.0239x over previous
#include <cuda_runtime.h>
#include <cstdint>

// Problem constants (fixed by reference)
#define BATCH   4
#define NTOK    8192
#define DIM     768
#define SEGW    512
#define NSEG    16
#define MG      256       // gathered (even) rows per segment
#define TM      128       // Q rows per CTA tile
#define KC      32        // phase-1 k-chunk width
#define NCHUNK  (DIM/KC)  // 24
#define THREADS 256

#define DCH     192       // phase-3 d chunk width
#define KSLAB   32        // phase-3 V slab rows
#define NIT3    32        // 4 d-chunks x 8 slabs, flattened

// Padded smem strides (floats). k-major: stride%8==4; V n-major: stride%32==8.
#define K_STRIDE 36
#define P_STRIDE 260
#define V_STRIDE 200      // 192 + 8

#define KCHF    (MG*K_STRIDE)     // 9216 floats per K buffer (3 buffers alias P)
#define KCHB    (KCHF*4)          // 36864 bytes
#define P_OFF   0
#define P_FLOATS (TM*P_STRIDE)    // 33280 floats = 133120 B >= 3*KCHB
#define V_OFF   P_FLOATS
#define V_OFFB  (V_OFF*4)         // 133120 bytes
#define VSLABF  (KSLAB*V_STRIDE)  // 6400 floats
#define VSLABB  (VSLABF*4)        // 25600 bytes
#define SMEM_FLOATS (V_OFF + 3*VSLABF)   // 52480
#define SMEM_BYTES  (SMEM_FLOATS * 4)    // 209920  (1 CTA/SM)

#define SCHED_FENCE() asm volatile("" ::: "memory")

__device__ __forceinline__ uint32_t smem_u32(const void* p) {
    uint32_t a;
    asm("{ .reg .u64 t; cvta.to.shared.u64 t, %1; cvt.u32.u64 %0, t; }" : "=r"(a) : "l"(p));
    return a;
}
__device__ __forceinline__ void cp16(uint32_t dst, const float* src) {
    asm volatile("cp.async.cg.shared.global [%0], [%1], 16;" :: "r"(dst), "l"(src) : "memory");
}
#define CP_COMMIT() asm volatile("cp.async.commit_group;" ::: "memory")
#define CP_WAIT(n)  asm volatile("cp.async.wait_group %0;" :: "n"(n) : "memory")

__device__ __forceinline__ void mma8(float c[4], const uint32_t a[4], const uint32_t b[2]) {
    asm volatile(
        "mma.sync.aligned.m16n8k8.row.col.f32.tf32.tf32.f32 "
        "{%0,%1,%2,%3}, {%4,%5,%6,%7}, {%8,%9}, {%0,%1,%2,%3};\n"
        : "+f"(c[0]), "+f"(c[1]), "+f"(c[2]), "+f"(c[3])
        : "r"(a[0]), "r"(a[1]), "r"(a[2]), "r"(a[3]), "r"(b[0]), "r"(b[1]));
}

__global__ __launch_bounds__(THREADS, 1)
void dilated_attn_kernel(const float* __restrict__ x, float* __restrict__ y)
{
    extern __shared__ float sm[];
    uint32_t* smu = (uint32_t*)sm;
    const uint32_t sb = smem_u32(sm);
    const int tid  = threadIdx.x;
    const int lane = tid & 31;
    const int wid  = tid >> 5;     // 0..7

    const int mtile = blockIdx.x & 1;       // 2 x 128-row tiles per problem
    const int pid   = blockIdx.x >> 1;      // 64 problems
    const long segbase = (long)(pid >> 4) * NTOK + (long)(pid & 15) * SEGW;
    const int  m0 = mtile * TM;

    // Warp layout (both GEMMs): 2 m-warps x 4 n-warps, 64-row warp tiles
    const int wm  = wid & 1;
    const int wn  = wid >> 1;
    const int ln4 = lane >> 2;   // fragment group 0..7
    const int lc4 = lane & 3;    // thread-in-group 0..3

    // ============ Phase 1: S = Q K^T (128 x 256), 3-stage cp.async K ring ============
    float acc[4][8][4];
    #pragma unroll
    for (int mt = 0; mt < 4; mt++)
        #pragma unroll
        for (int nt = 0; nt < 8; nt++)
            #pragma unroll
            for (int i = 0; i < 4; i++)
                acc[mt][nt][i] = 0.f;

    // Prologue: chunks 0,1 -> bufs 0,1
    #pragma unroll
    for (int c0 = 0; c0 < 2; c0++) {
        #pragma unroll
        for (int j = 0; j < 8; j++) {
            int idx = j * THREADS + tid;
            int r = idx >> 3, c4 = idx & 7;
            cp16(sb + (uint32_t)(c0 * KCHB + r * 144 + c4 * 16),
                 x + (size_t)(segbase + 2 * r) * DIM + c0 * KC + c4 * 4);
        }
        CP_COMMIT();
    }

    for (int kc = 0; kc < NCHUNK; kc++) {
        CP_WAIT(1);            // chunk kc landed (ours)
        __syncthreads();       // everyone's chunk kc visible + mma(kc-1) done by all

        const bool dofill = (kc + 2 < NCHUNK);
        const int kd = (kc + 2) * KC;
        const uint32_t nbb = (uint32_t)(((kc + 2) % 3) * KCHB);
        const uint32_t* cur = smu + (kc % 3) * KCHF;
        const uint32_t* abase = cur + (m0 + wm * 64 + ln4) * K_STRIDE + lc4;
        const uint32_t* bbase = cur + (wn * 64 + ln4) * K_STRIDE + lc4;

        uint32_t aF[2][4][4], bF[2][2];
        #pragma unroll
        for (int mt = 0; mt < 4; mt++) {
            const uint32_t* ba = abase + mt * 16 * K_STRIDE;
            aF[0][mt][0] = ba[0];
            aF[0][mt][1] = ba[8 * K_STRIDE];
            aF[0][mt][2] = ba[4];
            aF[0][mt][3] = ba[8 * K_STRIDE + 4];
        }
        bF[0][0] = bbase[0];
        bF[0][1] = bbase[4];

        #pragma unroll
        for (int ks = 0; ks < 4; ks++) {
            const int cs = ks & 1;
            #pragma unroll
            for (int nt = 0; nt < 8; nt++) {
                const int cb = nt & 1, nb = cb ^ 1;
                // next B fragment: (ks, nt+1), or (ks+1, 0) at row end
                if (nt < 7) {
                    const uint32_t* bb = bbase + (nt + 1) * 8 * K_STRIDE + ks * 8;
                    bF[nb][0] = bb[0];
                    bF[nb][1] = bb[4];
                } else if (ks < 3) {
                    const uint32_t* bb = bbase + (ks + 1) * 8;
                    bF[nb][0] = bb[0];
                    bF[nb][1] = bb[4];
                }
                // next A fragments: one mt per nt-group (nt=0..3)
                if (ks < 3 && nt < 4) {
                    const int mt = nt;
                    const uint32_t* ba = abase + mt * 16 * K_STRIDE + (ks + 1) * 8;
                    aF[cs ^ 1][mt][0] = ba[0];
                    aF[cs ^ 1][mt][1] = ba[8 * K_STRIDE];
                    aF[cs ^ 1][mt][2] = ba[4];
                    aF[cs ^ 1][mt][3] = ba[8 * K_STRIDE + 4];
                }
                // cp.async fill for chunk kc+2: one 16B copy per group across ks==0
                if (ks == 0 && dofill) {
                    int idx = nt * THREADS + tid;
                    int r = idx >> 3, c4 = idx & 7;
                    cp16(sb + nbb + (uint32_t)(r * 144 + c4 * 16),
                         x + (size_t)(segbase + 2 * r) * DIM + kd + c4 * 4);
                }
                // odd-row zero stores: spread across ks==1 (4 per chunk)
                if (ks == 1 && nt < 4) {
                    int i = (kc * 4 + nt) * THREADS + tid;   // 0..24575 over all chunks
                    int r = i / 192, c4 = i % 192;
                    long tok = segbase + 2 * (long)(m0 + r) + 1;
                    *(float4*)(y + (size_t)tok * DIM + c4 * 4) = make_float4(0.f, 0.f, 0.f, 0.f);
                }
                SCHED_FENCE();
                #pragma unroll
                for (int mt = 0; mt < 4; mt++)
                    mma8(acc[mt][nt], aF[cs][mt], bF[cb]);
                SCHED_FENCE();
            }
        }
        CP_COMMIT();           // one group per chunk (may be empty near tail)
    }
    __syncthreads();   // all K-ring reads done; P aliases the ring

    // Prefetch phase-3 V tiles t=0,1 now; fills land under the softmax.
    #pragma unroll
    for (int t0 = 0; t0 < 2; t0++) {
        const int rb = (t0 & 7) * KSLAB;
        const int dd = (t0 >> 3) * DCH;
        #pragma unroll
        for (int j = 0; j < 6; j++) {
            int idx = j * THREADS + tid;
            int row = idx / 48, c4 = idx % 48;
            cp16(sb + V_OFFB + (uint32_t)(t0 * VSLABB + row * 800 + c4 * 16),
                 x + (size_t)(segbase + 2 * (rb + row)) * DIM + dd + c4 * 4);
        }
        CP_COMMIT();
    }

    // ============ Phase 2: scale + softmax into P (raw fp32; mma truncates to tf32) ====
    const float scale = 0.03608439182435161f;  // 768^-0.5
    #pragma unroll
    for (int mt = 0; mt < 4; mt++)
        #pragma unroll
        for (int nt = 0; nt < 8; nt++) {
            int r = wm * 64 + mt * 16 + ln4;
            int c = wn * 64 + nt * 8 + 2 * lc4;
            sm[P_OFF + r * P_STRIDE + c]           = acc[mt][nt][0] * scale;
            sm[P_OFF + r * P_STRIDE + c + 1]       = acc[mt][nt][1] * scale;
            sm[P_OFF + (r + 8) * P_STRIDE + c]     = acc[mt][nt][2] * scale;
            sm[P_OFF + (r + 8) * P_STRIDE + c + 1] = acc[mt][nt][3] * scale;
        }
    __syncthreads();

    // Row softmax: warp w handles rows w*16..w*16+15
    #pragma unroll
    for (int rr = 0; rr < 16; rr++) {
        int row = wid * 16 + rr;
        float* pr = sm + P_OFF + row * P_STRIDE;
        float v[8];
        float mx = -1e30f;
        #pragma unroll
        for (int i = 0; i < 8; i++) { v[i] = pr[lane + 32 * i]; mx = fmaxf(mx, v[i]); }
        #pragma unroll
        for (int o = 16; o > 0; o >>= 1) mx = fmaxf(mx, __shfl_xor_sync(~0u, mx, o));
        float s = 0.f;
        #pragma unroll
        for (int i = 0; i < 8; i++) { v[i] = __expf(v[i] - mx); s += v[i]; }
        #pragma unroll
        for (int o = 16; o > 0; o >>= 1) s += __shfl_xor_sync(~0u, s, o);
        float inv = 1.f / s;
        #pragma unroll
        for (int i = 0; i < 8; i++) pr[lane + 32 * i] = v[i] * inv;
    }
    __syncthreads();

    // ============ Phase 3: out = P V (128 x 768), flattened (ch,sl) pipeline ============
    float o[4][6][4];
    #pragma unroll
    for (int mt = 0; mt < 4; mt++)
        #pragma unroll
        for (int nt = 0; nt < 6; nt++)
            #pragma unroll
            for (int i = 0; i < 4; i++)
                o[mt][nt][i] = 0.f;

    for (int t = 0; t < NIT3; t++) {
        const int sl = t & 7;
        const int d0 = (t >> 3) * DCH;

        CP_WAIT(1);
        __syncthreads();

        const bool dofill = (t + 2 < NIT3);
        const int t2 = t + 2;
        const int rb = (t2 & 7) * KSLAB;
        const int dd = (t2 >> 3) * DCH;
        const uint32_t nbb = V_OFFB + (uint32_t)((t2 % 3) * VSLABB);
        const uint32_t* vcur = smu + V_OFF + (t % 3) * VSLABF;
        const uint32_t* abase0 = smu + P_OFF + (wm * 64 + ln4) * P_STRIDE + sl * KSLAB + lc4;
        const uint32_t* bbase0 = vcur + lc4 * V_STRIDE + wn * 48 + ln4;

        uint32_t aF[2][4][4], bF[2][2];
        #pragma unroll
        for (int mt = 0; mt < 4; mt++) {
            const uint32_t* ba = abase0 + mt * 16 * P_STRIDE;
            aF[0][mt][0] = ba[0];
            aF[0][mt][1] = ba[8 * P_STRIDE];
            aF[0][mt][2] = ba[4];
            aF[0][mt][3] = ba[8 * P_STRIDE + 4];
        }
        bF[0][0] = bbase0[0];
        bF[0][1] = bbase0[4 * V_STRIDE];

        #pragma unroll
        for (int ks = 0; ks < 4; ks++) {
            const int cs = ks & 1;
            #pragma unroll
            for (int nt = 0; nt < 6; nt++) {
                const int cb = nt & 1, nb = cb ^ 1;
                // next B fragment: (ks, nt+1), or (ks+1, 0)
                if (nt < 5) {
                    const uint32_t* bb = bbase0 + ks * 8 * V_STRIDE + (nt + 1) * 8;
                    bF[nb][0] = bb[0];
                    bF[nb][1] = bb[4 * V_STRIDE];
                } else if (ks < 3) {
                    const uint32_t* bb = bbase0 + (ks + 1) * 8 * V_STRIDE;
                    bF[nb][0] = bb[0];
                    bF[nb][1] = bb[4 * V_STRIDE];
                }
                // next A fragments: one mt per nt-group (nt=0..3)
                if (ks < 3 && nt < 4) {
                    const int mt = nt;
                    const uint32_t* ba = abase0 + mt * 16 * P_STRIDE + (ks + 1) * 8;
                    aF[cs ^ 1][mt][0] = ba[0];
                    aF[cs ^ 1][mt][1] = ba[8 * P_STRIDE];
                    aF[cs ^ 1][mt][2] = ba[4];
                    aF[cs ^ 1][mt][3] = ba[8 * P_STRIDE + 4];
                }
                // cp.async fill for tile t+2: one 16B copy per group across ks==0
                if (ks == 0 && dofill) {
                    int idx = nt * THREADS + tid;
                    int row = idx / 48, c4 = idx % 48;
                    cp16(sb + nbb + (uint32_t)(row * 800 + c4 * 16),
                         x + (size_t)(segbase + 2 * (rb + row)) * DIM + dd + c4 * 4);
                }
                SCHED_FENCE();
                #pragma unroll
                for (int mt = 0; mt < 4; mt++)
                    mma8(o[mt][nt], aF[cs][mt], bF[cb]);
                SCHED_FENCE();
            }
        }
        CP_COMMIT();           // one group per tile (may be empty near tail)

        if (sl == 7) {
            // Epilogue for this d-chunk: even (gathered) rows get results
            #pragma unroll
            for (int mt = 0; mt < 4; mt++)
                #pragma unroll
                for (int nt = 0; nt < 6; nt++) {
                    int gr = m0 + wm * 64 + mt * 16 + ln4;
                    int c  = d0 + wn * 48 + nt * 8 + 2 * lc4;
                    long tok0 = segbase + 2 * (long)gr;
                    long tok1 = segbase + 2 * (long)(gr + 8);
                    *(float2*)(y + (size_t)tok0 * DIM + c) = make_float2(o[mt][nt][0], o[mt][nt][1]);
                    *(float2*)(y + (size_t)tok1 * DIM + c) = make_float2(o[mt][nt][2], o[mt][nt][3]);
                    #pragma unroll
                    for (int i = 0; i < 4; i++) o[mt][nt][i] = 0.f;
                }
        }
    }
}

extern "C" void kernel_launch(void* const* d_in, const int* in_sizes, int n_in,
                              void* d_out, int out_size)
{
    const float* x = (const float*)d_in[0];
    float* y = (float*)d_out;
    cudaFuncSetAttribute(dilated_attn_kernel,
                         cudaFuncAttributeMaxDynamicSharedMemorySize, SMEM_BYTES);
    dilated_attn_kernel<<<BATCH * NSEG * 2, THREADS, SMEM_BYTES>>>(x, y);
}

// round 15
// speedup vs baseline: 1.7360x; 1.2362x over previous
#include <cuda_runtime.h>
#include <cuda_fp16.h>
#include <cstdint>

// Problem constants (fixed by reference)
#define BATCH   4
#define NTOK    8192
#define DIM     768
#define SEGW    512
#define NSEG    16
#define MG      256       // gathered (even) rows per segment
#define TM      128       // Q rows per CTA tile
#define KC      32        // phase-1 k-dims per chunk (2 x k16 steps)
#define NCHUNK  24
#define THREADS 256

#define DCH     192       // phase-3 d chunk width
#define KSLAB   64        // phase-3 k rows per tile (4 x k16 steps)
#define NIT3    16        // 4 d-chunks x 4 slabs

// Strides in 32-bit words (1 word = half2). Conflict-free residues:
// K: 80B = 16 mod 128; P: 528B = 16 mod 128; V: 800B = 32 mod 128.
#define KSW  20
#define PSW  132
#define VSW  200

#define KCHW  (MG*KSW)        // 5120 words per K ring slot (20480 B)
#define V_OFFW 16896          // V ring start (byte 67584), after P region
#define VSLABW (32*VSW)       // 6400 words per V slot (25600 B)
#define RED1W  36096          // redmax (byte 144384)
#define RED2W  36608          // redsum (byte 146432)
#define SMEM_BYTES 148480

#define SCHED_FENCE() asm volatile("" ::: "memory")

__device__ __forceinline__ uint32_t h2u(float a, float b) {
    __half2 h = __floats2half2_rn(a, b);
    return *reinterpret_cast<uint32_t*>(&h);
}

__device__ __forceinline__ void mma16(float c[4], const uint32_t a[4], const uint32_t b[2]) {
    asm volatile(
        "mma.sync.aligned.m16n8k16.row.col.f32.f16.f16.f32 "
        "{%0,%1,%2,%3}, {%4,%5,%6,%7}, {%8,%9}, {%0,%1,%2,%3};\n"
        : "+f"(c[0]), "+f"(c[1]), "+f"(c[2]), "+f"(c[3])
        : "r"(a[0]), "r"(a[1]), "r"(a[2]), "r"(a[3]), "r"(b[0]), "r"(b[1]));
}

__global__ __launch_bounds__(THREADS, 1)
void dilated_attn_kernel(const float* __restrict__ x, float* __restrict__ y)
{
    extern __shared__ float sm[];
    uint32_t* smu = (uint32_t*)sm;
    const int tid  = threadIdx.x;
    const int lane = tid & 31;
    const int wid  = tid >> 5;     // 0..7

    const int mtile = blockIdx.x & 1;       // 2 x 128-row tiles per problem
    const int pid   = blockIdx.x >> 1;      // 64 problems
    const long segbase = (long)(pid >> 4) * NTOK + (long)(pid & 15) * SEGW;
    const int  m0 = mtile * TM;

    // Warp layout (both GEMMs): 2 m-warps x 4 n-warps, 64-row warp tiles
    const int wm  = wid & 1;
    const int wn  = wid >> 1;
    const int ln4 = lane >> 2;   // fragment group 0..7
    const int lc4 = lane & 3;    // thread-in-group 0..3

    const float* xrow = x + (size_t)(segbase + 2 * tid) * DIM;  // this thread's K/V fill row

    // ============ Phase 1: S = Q K^T (128 x 256 fp32 acc), fp16 tiles, 3-slot ring ====
    float acc[4][8][4];
    #pragma unroll
    for (int mt = 0; mt < 4; mt++)
        #pragma unroll
        for (int nt = 0; nt < 8; nt++)
            #pragma unroll
            for (int i = 0; i < 4; i++)
                acc[mt][nt][i] = 0.f;

    // Prologue: chunks 0,1 filled directly (LDG -> cvt -> STS), slots 0,1
    #pragma unroll
    for (int c0 = 0; c0 < 2; c0++) {
        #pragma unroll
        for (int u = 0; u < 4; u++) {
            const float* src = xrow + c0 * KC + u * 8;
            float4 lo = *(const float4*)src;
            float4 hi = *(const float4*)(src + 4);
            uint4 w = make_uint4(h2u(lo.x, lo.y), h2u(lo.z, lo.w),
                                 h2u(hi.x, hi.y), h2u(hi.z, hi.w));
            *(uint4*)(smu + c0 * KCHW + tid * KSW + u * 4) = w;
        }
    }

    float4 stg[8];   // LDG staging: chunk kc+2 (4 units x 2 float4)
    for (int kc = 0; kc < NCHUNK; kc++) {
        __syncthreads();   // chunk kc visible; mma(kc-1) done by all
        const bool doSTS = (kc >= 1) && (kc + 1 < NCHUNK);
        const bool doLDG = (kc + 2 < NCHUNK);
        uint32_t* stsDst = smu + ((kc + 1) % 3) * KCHW + tid * KSW;
        const int kdN = (kc + 2) * KC;
        const uint32_t* cur = smu + (kc % 3) * KCHW;
        const uint32_t* abase = cur + (m0 + wm * 64 + ln4) * KSW + lc4;
        const uint32_t* bbase = cur + (wn * 64 + ln4) * KSW + lc4;

        uint32_t aF[2][4][4], bF[2][2];
        #pragma unroll
        for (int mt = 0; mt < 4; mt++) {
            const uint32_t* ba = abase + mt * 320;
            aF[0][mt][0] = ba[0];
            aF[0][mt][1] = ba[160];
            aF[0][mt][2] = ba[4];
            aF[0][mt][3] = ba[164];
        }
        bF[0][0] = bbase[0];
        bF[0][1] = bbase[4];

        #pragma unroll
        for (int ks = 0; ks < 2; ks++) {
            #pragma unroll
            for (int nt = 0; nt < 8; nt++) {
                const int cb = (ks * 8 + nt) & 1, nb = cb ^ 1;
                // next B fragment: (ks, nt+1) or (1, 0)
                if (nt < 7) {
                    const uint32_t* bb = bbase + (nt + 1) * 160 + ks * 8;
                    bF[nb][0] = bb[0];
                    bF[nb][1] = bb[4];
                } else if (ks == 0) {
                    const uint32_t* bb = bbase + 8;
                    bF[nb][0] = bb[0];
                    bF[nb][1] = bb[4];
                }
                // next A fragments for ks=1: one mt per group at ks==0, nt<4
                if (ks == 0 && nt < 4) {
                    const int mt = nt;
                    const uint32_t* ba = abase + mt * 320 + 8;
                    aF[1][mt][0] = ba[0];
                    aF[1][mt][1] = ba[160];
                    aF[1][mt][2] = ba[4];
                    aF[1][mt][3] = ba[164];
                }
                // STS chunk kc+1 (from stage): 4 units at ks==0, nt<4
                if (ks == 0 && nt < 4 && doSTS) {
                    const int u = nt;
                    float4 lo = stg[2 * u], hi = stg[2 * u + 1];
                    uint4 w = make_uint4(h2u(lo.x, lo.y), h2u(lo.z, lo.w),
                                         h2u(hi.x, hi.y), h2u(hi.z, hi.w));
                    *(uint4*)(stsDst + u * 4) = w;
                }
                // LDG chunk kc+2: 8 loads spread over ks0/nt>=4 and ks1/nt<4
                if (doLDG && ((ks == 0 && nt >= 4) || (ks == 1 && nt < 4))) {
                    const int l = (ks == 0) ? (nt - 4) : (nt + 4);
                    stg[l] = *(const float4*)(xrow + kdN + l * 4);
                }
                // odd-row zero stores: 4 per chunk at ks==1, nt>=4
                if (ks == 1 && nt >= 4) {
                    int i = (kc * 4 + (nt - 4)) * THREADS + tid;
                    int r = i / 192, c4 = i % 192;
                    long tok = segbase + 2 * (long)(m0 + r) + 1;
                    *(float4*)(y + (size_t)tok * DIM + c4 * 4) = make_float4(0.f, 0.f, 0.f, 0.f);
                }
                SCHED_FENCE();
                #pragma unroll
                for (int mt = 0; mt < 4; mt++)
                    mma16(acc[mt][nt], aF[ks][mt], bF[cb]);
                SCHED_FENCE();
            }
        }
    }

    // Prefetch phase-3 V tile 0 (region disjoint from K ring); lands under softmax.
    float4 vstg[12];
    #pragma unroll
    for (int j = 0; j < 6; j++) {
        int idx = j * THREADS + tid;
        int p = idx / 48, c4 = idx % 48;
        const float* s0 = x + (size_t)(segbase + 4 * p) * DIM + c4 * 4;
        vstg[2 * j]     = *(const float4*)s0;
        vstg[2 * j + 1] = *(const float4*)(s0 + 2 * DIM);
    }

    __syncthreads();   // all K-ring reads done; P (overlapping ring) may be written

    // ============ Phase 2: softmax in registers; P written once as half2 ============
    const float scale = 0.03608439182435161f;  // 768^-0.5
    #pragma unroll
    for (int mt = 0; mt < 4; mt++)
        #pragma unroll
        for (int nt = 0; nt < 8; nt++)
            #pragma unroll
            for (int i = 0; i < 4; i++)
                acc[mt][nt][i] *= scale;

    float* red1 = (float*)(smu + RED1W);
    float* red2 = (float*)(smu + RED2W);
    float mxv[8], inv[8];
    // local max per row-slot (s = mt*2 + h), then lc4-group shfl, then cross-wn via smem
    #pragma unroll
    for (int mt = 0; mt < 4; mt++) {
        float m0v = -1e30f, m1v = -1e30f;
        #pragma unroll
        for (int nt = 0; nt < 8; nt++) {
            m0v = fmaxf(m0v, fmaxf(acc[mt][nt][0], acc[mt][nt][1]));
            m1v = fmaxf(m1v, fmaxf(acc[mt][nt][2], acc[mt][nt][3]));
        }
        mxv[mt * 2]     = m0v;
        mxv[mt * 2 + 1] = m1v;
    }
    #pragma unroll
    for (int s = 0; s < 8; s++) {
        mxv[s] = fmaxf(mxv[s], __shfl_xor_sync(~0u, mxv[s], 1));
        mxv[s] = fmaxf(mxv[s], __shfl_xor_sync(~0u, mxv[s], 2));
    }
    if (lc4 == 0) {
        #pragma unroll
        for (int s = 0; s < 8; s++) {
            int row = wm * 64 + (s >> 1) * 16 + (s & 1) * 8 + ln4;
            red1[wn * 128 + row] = mxv[s];
        }
    }
    __syncthreads();
    #pragma unroll
    for (int s = 0; s < 8; s++) {
        int row = wm * 64 + (s >> 1) * 16 + (s & 1) * 8 + ln4;
        float m = fmaxf(fmaxf(red1[row], red1[128 + row]),
                        fmaxf(red1[256 + row], red1[384 + row]));
        mxv[s] = m;
    }
    // exp + sum
    #pragma unroll
    for (int mt = 0; mt < 4; mt++) {
        float s0v = 0.f, s1v = 0.f;
        #pragma unroll
        for (int nt = 0; nt < 8; nt++) {
            acc[mt][nt][0] = __expf(acc[mt][nt][0] - mxv[mt * 2]);
            acc[mt][nt][1] = __expf(acc[mt][nt][1] - mxv[mt * 2]);
            acc[mt][nt][2] = __expf(acc[mt][nt][2] - mxv[mt * 2 + 1]);
            acc[mt][nt][3] = __expf(acc[mt][nt][3] - mxv[mt * 2 + 1]);
            s0v += acc[mt][nt][0] + acc[mt][nt][1];
            s1v += acc[mt][nt][2] + acc[mt][nt][3];
        }
        inv[mt * 2]     = s0v;
        inv[mt * 2 + 1] = s1v;
    }
    #pragma unroll
    for (int s = 0; s < 8; s++) {
        inv[s] += __shfl_xor_sync(~0u, inv[s], 1);
        inv[s] += __shfl_xor_sync(~0u, inv[s], 2);
    }
    if (lc4 == 0) {
        #pragma unroll
        for (int s = 0; s < 8; s++) {
            int row = wm * 64 + (s >> 1) * 16 + (s & 1) * 8 + ln4;
            red2[wn * 128 + row] = inv[s];
        }
    }
    __syncthreads();
    #pragma unroll
    for (int s = 0; s < 8; s++) {
        int row = wm * 64 + (s >> 1) * 16 + (s & 1) * 8 + ln4;
        inv[s] = 1.f / (red2[row] + red2[128 + row] + red2[256 + row] + red2[384 + row]);
    }
    // write P as half2 (row r, cols c,c+1)
    #pragma unroll
    for (int mt = 0; mt < 4; mt++)
        #pragma unroll
        for (int nt = 0; nt < 8; nt++) {
            int r0 = wm * 64 + mt * 16 + ln4;
            int cw = (wn * 64 + nt * 8 + 2 * lc4) >> 1;   // word column
            smu[r0 * PSW + cw]       = h2u(acc[mt][nt][0] * inv[mt * 2],
                                           acc[mt][nt][1] * inv[mt * 2]);
            smu[(r0 + 8) * PSW + cw] = h2u(acc[mt][nt][2] * inv[mt * 2 + 1],
                                           acc[mt][nt][3] * inv[mt * 2 + 1]);
        }

    // V tile 0 -> slot 0; direct-fill tile 1 -> slot 1
    #pragma unroll
    for (int j = 0; j < 6; j++) {
        int idx = j * THREADS + tid;
        int p = idx / 48, c4 = idx % 48;
        float4 lo = vstg[2 * j], hi = vstg[2 * j + 1];
        uint4 w = make_uint4(h2u(lo.x, hi.x), h2u(lo.y, hi.y),
                             h2u(lo.z, hi.z), h2u(lo.w, hi.w));
        *(uint4*)(smu + V_OFFW + p * VSW + c4 * 4) = w;
    }
    #pragma unroll
    for (int j = 0; j < 6; j++) {   // tile 1: sl=1 -> k rows 64.., d-chunk 0
        int idx = j * THREADS + tid;
        int p = idx / 48, c4 = idx % 48;
        const float* s0 = x + (size_t)(segbase + 128 + 4 * p) * DIM + c4 * 4;
        float4 lo = *(const float4*)s0;
        float4 hi = *(const float4*)(s0 + 2 * DIM);
        uint4 w = make_uint4(h2u(lo.x, hi.x), h2u(lo.y, hi.y),
                             h2u(lo.z, hi.z), h2u(lo.w, hi.w));
        *(uint4*)(smu + V_OFFW + VSLABW + p * VSW + c4 * 4) = w;
    }

    // ============ Phase 3: D = P V (128 x 768), flattened (ch,sl), 3-slot V ring ======
    float o[4][6][4];
    #pragma unroll
    for (int mt = 0; mt < 4; mt++)
        #pragma unroll
        for (int nt = 0; nt < 6; nt++)
            #pragma unroll
            for (int i = 0; i < 4; i++)
                o[mt][nt][i] = 0.f;

    for (int t = 0; t < NIT3; t++) {
        __syncthreads();
        const int sl = t & 3;
        const int d0 = (t >> 2) * DCH;
        const bool doSTS = (t >= 1) && (t + 1 < NIT3);
        const bool doLDG = (t + 2 < NIT3);
        uint32_t* stsDst = smu + V_OFFW + ((t + 1) % 3) * VSLABW;
        const int t2sl = (t + 2) & 3;
        const int t2d0 = ((t + 2) >> 2) * DCH;
        const uint32_t* vcur = smu + V_OFFW + (t % 3) * VSLABW;
        const uint32_t* abase = smu + (wm * 64 + ln4) * PSW + sl * 32 + lc4;
        const uint32_t* bbase = vcur + lc4 * VSW + wn * 48 + ln4;

        uint32_t aF[2][4][4], bF[2][2];
        #pragma unroll
        for (int mt = 0; mt < 4; mt++) {
            const uint32_t* ba = abase + mt * 2112;
            aF[0][mt][0] = ba[0];
            aF[0][mt][1] = ba[1056];
            aF[0][mt][2] = ba[4];
            aF[0][mt][3] = ba[1060];
        }
        bF[0][0] = bbase[0];
        bF[0][1] = bbase[800];

        #pragma unroll
        for (int ks = 0; ks < 4; ks++) {
            const int cs = ks & 1;
            #pragma unroll
            for (int nt = 0; nt < 6; nt++) {
                const int cb = nt & 1, nb = cb ^ 1;
                if (nt < 5) {
                    const uint32_t* bb = bbase + ks * 8 * VSW + (nt + 1) * 8;
                    bF[nb][0] = bb[0];
                    bF[nb][1] = bb[800];
                } else if (ks < 3) {
                    const uint32_t* bb = bbase + (ks + 1) * 8 * VSW;
                    bF[nb][0] = bb[0];
                    bF[nb][1] = bb[800];
                }
                if (ks < 3 && nt < 4) {
                    const int mt = nt;
                    const uint32_t* ba = abase + mt * 2112 + (ks + 1) * 8;
                    aF[cs ^ 1][mt][0] = ba[0];
                    aF[cs ^ 1][mt][1] = ba[1056];
                    aF[cs ^ 1][mt][2] = ba[4];
                    aF[cs ^ 1][mt][3] = ba[1060];
                }
                // STS tile t+1 (6 units at ks==0)
                if (ks == 0 && doSTS) {
                    int idx = nt * THREADS + tid;
                    int p = idx / 48, c4 = idx % 48;
                    float4 lo = vstg[2 * nt], hi = vstg[2 * nt + 1];
                    uint4 w = make_uint4(h2u(lo.x, hi.x), h2u(lo.y, hi.y),
                                         h2u(lo.z, hi.z), h2u(lo.w, hi.w));
                    *(uint4*)(stsDst + p * VSW + c4 * 4) = w;
                }
                // LDG tile t+2 (12 loads at ks in {1,2})
                if (doLDG && (ks == 1 || ks == 2)) {
                    const int l = (ks - 1) * 6 + nt;
                    const int u = l >> 1, which = l & 1;
                    int idx = u * THREADS + tid;
                    int p = idx / 48, c4 = idx % 48;
                    const float* s0 = x + (size_t)(segbase + 2 * (t2sl * 64 + 2 * p) + 2 * which) * DIM
                                        + t2d0 + c4 * 4;
                    vstg[2 * u + which] = *(const float4*)s0;
                }
                SCHED_FENCE();
                #pragma unroll
                for (int mt = 0; mt < 4; mt++)
                    mma16(o[mt][nt], aF[cs][mt], bF[cb]);
                SCHED_FENCE();
            }
        }

        if (sl == 3) {
            // Epilogue for this d-chunk: even (gathered) rows get results
            #pragma unroll
            for (int mt = 0; mt < 4; mt++)
                #pragma unroll
                for (int nt = 0; nt < 6; nt++) {
                    int gr = m0 + wm * 64 + mt * 16 + ln4;
                    int c  = d0 + wn * 48 + nt * 8 + 2 * lc4;
                    long tok0 = segbase + 2 * (long)gr;
                    long tok1 = segbase + 2 * (long)(gr + 8);
                    *(float2*)(y + (size_t)tok0 * DIM + c) = make_float2(o[mt][nt][0], o[mt][nt][1]);
                    *(float2*)(y + (size_t)tok1 * DIM + c) = make_float2(o[mt][nt][2], o[mt][nt][3]);
                    #pragma unroll
                    for (int i = 0; i < 4; i++) o[mt][nt][i] = 0.f;
                }
        }
    }
}

extern "C" void kernel_launch(void* const* d_in, const int* in_sizes, int n_in,
                              void* d_out, int out_size)
{
    const float* x = (const float*)d_in[0];
    float* y = (float*)d_out;
    cudaFuncSetAttribute(dilated_attn_kernel,
                         cudaFuncAttributeMaxDynamicSharedMemorySize, SMEM_BYTES);
    dilated_attn_kernel<<<BATCH * NSEG * 2, THREADS, SMEM_BYTES>>>(x, y);
}